// round 7
// baseline (speedup 1.0000x reference)
#include <cuda_runtime.h>
#include <cuda_bf16.h>
#include <cstdint>

// ===========================================================================
// B=4, C_IN=256, C=128, H=W=64, HW=4096. out [4,128,128,128] f32.
// ALL dense ops on mma.sync bf16 HMMA with 2-term split (K'=3K):
//   A pattern (hi,lo,hi)  x  B pattern (hi,hi,lo)
//   => Ahi.Bhi + Alo.Bhi + Ahi.Blo  (error ~2^-18)
// Engine: 128x128 tile, 8 warps, ldmatrix.x4 fragments, cp.async 2-stage.
// Convs: implicit GEMM, on-the-fly split im2col in SMEM.
// ===========================================================================

#define F_RES1 0LL
#define F_RES2 (F_RES1 + 2097152)
#define F_SIM  (F_RES2 + 2097152)
#define F_DIFC (F_SIM  + 16384)
#define F_ABSD (F_DIFC + 4194304)
#define F_SIMP (F_ABSD + 2097152)
#define F_R    (F_SIMP + 524288)
#define F_B0B1 (F_R    + 2097152)
#define F_DIF  (F_B0B1 + 2097152)
#define F_INC  (F_DIF  + 2097152)
#define F_LOG  (F_INC  + 2097152)      /* logitsT [B,4096,1024] */
#define F_ACAT (F_LOG  + 16777216)
#define F_FUSE (F_ACAT + 4194304)
#define F_PAR  (F_FUSE + 2097152)
#define F_TOTAL (F_PAR + 8192)

__device__ float g_scratch[F_TOTAL];

// bf16 scratch (element offsets; all multiples of 8 for 16B alignment)
#define W_T1W3   0LL        /* [128,768]   */
#define W_T2W3   98304LL
#define W_RESW3  196608LL   /* [128,768]   */
#define W_FUW3   294912LL   /* [128,768]   */
#define W_DFUW3  393216LL   /* [128,384]   */
#define W_B0W3   442368LL   /* [64,3456]   */
#define W_B1W3   663552LL   /* [64,9600]   */
#define W_BR1W3  1277952LL  /* [128,3456]  */
#define W_BR2W3  1720320LL  /* [128,9600]  */
#define G_ATTN3  2949120LL  /* [4,1024,384]  */
#define G_INCT3  4521984LL  /* [4,4096,384]  */
#define G_ATTNT3 10813440LL /* [4,128,3072]  */
#define G_AT3    12386304LL /* [4,4096,3072] */
#define G_T3A    62717952LL /* [4,4096,768]  (t1 / difcat / acat) */
#define G_T3B    75300864LL /* [4,4096,768]  (t2) */
#define G_BBT3   87883776LL /* [4,4096,384]  */
#define G_TOTAL  94175232LL

__device__ __align__(256) __nv_bfloat16 g_bf[G_TOTAL];

// ------------------------------ helpers ------------------------------------
__device__ __forceinline__ uint32_t smem_u32(const void* p) {
    uint32_t a;
    asm("{ .reg .u64 t; cvta.to.shared.u64 t, %1; cvt.u32.u64 %0, t; }"
        : "=r"(a) : "l"(p));
    return a;
}
__device__ __forceinline__ void bsplit(float x, __nv_bfloat16& h, __nv_bfloat16& l) {
    h = __float2bfloat16(x);
    l = __float2bfloat16(x - __bfloat162float(h));
}
__device__ __forceinline__ unsigned short bfbits(__nv_bfloat16 h) {
    return reinterpret_cast<unsigned short&>(h);
}
#define CP_ASYNC(dst, src) asm volatile( \
    "cp.async.cg.shared.global [%0], [%1], 16;" :: "r"(dst), "l"(src))
#define CP_COMMIT() asm volatile("cp.async.commit_group;" ::: "memory")
#define CP_WAIT1()  asm volatile("cp.async.wait_group 1;" ::: "memory")
#define CP_WAIT0()  asm volatile("cp.async.wait_group 0;" ::: "memory")
#define LDM_X4(r0, r1, r2, r3, a) asm volatile( \
    "ldmatrix.sync.aligned.m8n8.x4.shared.b16 {%0,%1,%2,%3}, [%4];" \
    : "=r"(r0), "=r"(r1), "=r"(r2), "=r"(r3) : "r"(a))
#define MMA16816(d, a, bfr) asm volatile( \
    "mma.sync.aligned.m16n8k16.row.col.f32.bf16.bf16.f32 " \
    "{%0,%1,%2,%3}, {%4,%5,%6,%7}, {%8,%9}, {%0,%1,%2,%3};" \
    : "+f"((d)[0]), "+f"((d)[1]), "+f"((d)[2]), "+f"((d)[3]) \
    : "r"((a)[0]), "r"((a)[1]), "r"((a)[2]), "r"((a)[3]), \
      "r"((bfr)[0]), "r"((bfr)[1]))

// ===========================================================================
// hmma_gemm: 128x128 tile, 8 warps (32m x 64n per warp), chunk k=32,
// cp.async double-buffer, ldmatrix fragments.
// C[b,m,n] = sum_k A3[m,k]*B3[n,k] (+bias, relu-affine, resid)
// A3 [Mtot,Kp], B3 [Ntot,Kp] bf16 row-major; Kp % 32 == 0.
// grid = (N/128, M/128, B)
// ===========================================================================
__global__ void __launch_bounds__(256) hmma_gemm(
    const __nv_bfloat16* __restrict__ A3, const __nv_bfloat16* __restrict__ B3,
    float* __restrict__ C,
    const float* __restrict__ bias, const float* __restrict__ scale,
    const float* __restrict__ off, const float* __restrict__ resid,
    int Kp, int Ncols,
    long long Abs, long long Bbs, long long Cbs, long long Rbs)
{
    __shared__ __align__(16) __nv_bfloat16 As[2][128][40];
    __shared__ __align__(16) __nv_bfloat16 Bs[2][128][40];
    const int t = threadIdx.x, lane = t & 31, wid = t >> 5;
    const int wm = wid & 3;        // 4 warps along m (32 rows each)
    const int wn = wid >> 2;       // 2 warps along n (64 cols each)
    const int b  = blockIdx.z;
    const int m0 = blockIdx.y * 128;
    const int n0 = blockIdx.x * 128;
    const __nv_bfloat16* Ab = A3 + (long long)b * Abs + (long long)m0 * Kp;
    const __nv_bfloat16* Bb = B3 + (long long)b * Bbs + (long long)n0 * Kp;
    const uint32_t sA = smem_u32(&As[0][0][0]);
    const uint32_t sB = smem_u32(&Bs[0][0][0]);

    float acc[2][8][4];
#pragma unroll
    for (int i = 0; i < 2; i++)
#pragma unroll
        for (int j = 0; j < 8; j++)
#pragma unroll
            for (int r = 0; r < 4; r++) acc[i][j][r] = 0.f;

    const int row4 = t >> 2, kq4 = t & 3;
    auto ldch = [&](int buf, int c) {
#pragma unroll
        for (int r = 0; r < 2; r++) {
            int f = t + 256 * r;
            int row = f >> 2, kq = f & 3;
            CP_ASYNC(sA + (uint32_t)(buf * 10240 + row * 80 + kq * 16),
                     Ab + (long long)row * Kp + c * 32 + kq * 8);
        }
#pragma unroll
        for (int r = 0; r < 2; r++) {
            int f = t + 256 * r;
            int row = f >> 2, kq = f & 3;
            CP_ASYNC(sB + (uint32_t)(buf * 10240 + row * 80 + kq * 16),
                     Bb + (long long)row * Kp + c * 32 + kq * 8);
        }
        CP_COMMIT();
    };
    (void)row4; (void)kq4;

    const int nch = Kp >> 5;
    ldch(0, 0);
    for (int c = 0; c < nch; c++) {
        const int buf = c & 1;
        const bool more = (c + 1) < nch;
        if (more) { ldch(buf ^ 1, c + 1); CP_WAIT1(); } else { CP_WAIT0(); }
        __syncthreads();
#pragma unroll
        for (int ks = 0; ks < 2; ks++) {
            const int kb = ks * 16;
            uint32_t af[2][4];
#pragma unroll
            for (int i = 0; i < 2; i++) {
                int row = wm * 32 + i * 16 + (lane & 7) + ((lane >> 3) & 1) * 8;
                int col = kb + ((lane >> 4) & 1) * 8;
                LDM_X4(af[i][0], af[i][1], af[i][2], af[i][3],
                       sA + (uint32_t)(buf * 10240 + row * 80 + col * 2));
            }
            uint32_t bfr[8][2];
#pragma unroll
            for (int jp = 0; jp < 4; jp++) {
                int n = wn * 64 + jp * 16 + (lane & 7) + ((lane >> 4) & 1) * 8;
                int k = kb + ((lane >> 3) & 1) * 8;
                LDM_X4(bfr[2 * jp][0], bfr[2 * jp][1],
                       bfr[2 * jp + 1][0], bfr[2 * jp + 1][1],
                       sB + (uint32_t)(buf * 10240 + n * 80 + k * 2));
            }
#pragma unroll
            for (int i = 0; i < 2; i++)
#pragma unroll
                for (int j = 0; j < 8; j++)
                    MMA16816(acc[i][j], af[i], bfr[j]);
        }
        __syncthreads();
    }

    float* Cb = C + (long long)b * Cbs;
    const float* Rb = resid ? resid + (long long)b * Rbs : nullptr;
#pragma unroll
    for (int i = 0; i < 2; i++)
#pragma unroll
        for (int h = 0; h < 2; h++) {
            int m = m0 + wm * 32 + i * 16 + (lane >> 2) + h * 8;
            float bi = bias  ? bias[m]  : 0.f;
            float sc = scale ? scale[m] : 1.f;
            float ofv = off  ? off[m]   : 0.f;
            float* crow = Cb + (long long)m * Ncols;
            const float* rrow = Rb ? Rb + (long long)m * Ncols : nullptr;
#pragma unroll
            for (int j = 0; j < 8; j++) {
                int col = n0 + wn * 64 + j * 8 + (lane & 3) * 2;
                float2 v = make_float2(acc[i][j][h * 2 + 0] + bi,
                                       acc[i][j][h * 2 + 1] + bi);
                if (scale) {
                    v.x = fmaxf(v.x, 0.f) * sc + ofv;
                    v.y = fmaxf(v.y, 0.f) * sc + ofv;
                }
                if (rrow) {
                    float2 rv = *(const float2*)(rrow + col);
                    v.x += rv.x; v.y += rv.y;
                }
                *(float2*)(crow + col) = v;
            }
        }
}

// ===========================================================================
// hconv: implicit-GEMM conv KSxKS (pad KS/2), Cin=128, input [B,128,64,64] f32.
// A = pre-split weights [MT, 3*128*KS*KS] bf16 (hi,lo,hi).
// B tile built on the fly in SMEM: pattern (hi,hi,lo).
// MT in {64,128}. grid = (4096/128, 1, B), 256 threads.
// ===========================================================================
template <int KS, int MT>
__global__ void __launch_bounds__(256) hconv(
    const float* __restrict__ in, const __nv_bfloat16* __restrict__ W3,
    float* __restrict__ out,
    const float* __restrict__ bias, const float* __restrict__ scale,
    const float* __restrict__ off, long long out_bstride)
{
    constexpr int KS2   = KS * KS;
    constexpr int P     = KS / 2;
    constexpr int KCORE = 128 * KS2;
    constexpr int Kp    = 3 * KCORE;
    constexpr int WM_N  = MT / 32;       // m-warps
    constexpr int WN_N  = 8 / WM_N;      // n-warps
    constexpr int NJ    = 128 / (WN_N * 8);
    __shared__ __align__(16) __nv_bfloat16 As[2][MT][40];
    __shared__ __align__(16) __nv_bfloat16 Bs[2][128][40];
    const int t = threadIdx.x, lane = t & 31, wid = t >> 5;
    const int wm = wid % WM_N, wn = wid / WM_N;
    const int b  = blockIdx.z;
    const int n0 = blockIdx.x * 128;
    const float* inb = in + (long long)b * 524288;
    const uint32_t sA = smem_u32(&As[0][0][0]);
    const uint32_t sB = smem_u32(&Bs[0][0][0]);

    float acc[2][NJ][4];
#pragma unroll
    for (int i = 0; i < 2; i++)
#pragma unroll
        for (int j = 0; j < NJ; j++)
#pragma unroll
            for (int r = 0; r < 4; r++) acc[i][j][r] = 0.f;

    auto ldA = [&](int buf, int c) {
#pragma unroll
        for (int r = 0; r < MT / 64; r++) {
            int f = t + 256 * r;
            int row = f >> 2, kq = f & 3;
            CP_ASYNC(sA + (uint32_t)(buf * (MT * 80) + row * 80 + kq * 16),
                     W3 + (long long)row * Kp + c * 32 + kq * 8);
        }
        CP_COMMIT();
    };

    // B fill: thread -> pixel (t&127), k-half (t>>7); 16 values, 2 STS.128
    const int pix   = t & 127;
    const int kh    = (t >> 7) * 16;
    const int gp    = n0 + pix;
    const int ybase = gp >> 6;
    const int xbase = gp & 63;
    auto fillB = [&](int buf, int c) {
        uint32_t pk[8];
        const int kc0 = c * 32 + kh;
#pragma unroll
        for (int q = 0; q < 16; q++) {
            int kq = kc0 + q;
            int part = (kq >= KCORE) + (kq >= 2 * KCORE);
            int kk = kq - part * KCORE;
            int ci = kk / KS2;
            int tap = kk - ci * KS2;
            int dy = tap / KS - P, dx = tap - (tap / KS) * KS - P;
            int y = ybase + dy, x = xbase + dx;
            float v = 0.f;
            if ((unsigned)y < 64u && (unsigned)x < 64u)
                v = inb[ci * 4096 + y * 64 + x];
            __nv_bfloat16 h, l; bsplit(v, h, l);
            unsigned short bits = bfbits(part < 2 ? h : l);
            if (q & 1) pk[q >> 1] |= ((uint32_t)bits << 16);
            else       pk[q >> 1]  = (uint32_t)bits;
        }
        uint32_t dst = sB + (uint32_t)(buf * 10240 + pix * 80 + kh * 2);
        asm volatile("st.shared.v4.b32 [%0], {%1,%2,%3,%4};"
                     :: "r"(dst), "r"(pk[0]), "r"(pk[1]), "r"(pk[2]), "r"(pk[3]));
        asm volatile("st.shared.v4.b32 [%0], {%1,%2,%3,%4};"
                     :: "r"(dst + 16), "r"(pk[4]), "r"(pk[5]), "r"(pk[6]), "r"(pk[7]));
    };

    const int nch = Kp >> 5;
    ldA(0, 0);
    fillB(0, 0);
    for (int c = 0; c < nch; c++) {
        const int buf = c & 1;
        const bool more = (c + 1) < nch;
        if (more) {
            ldA(buf ^ 1, c + 1);
            fillB(buf ^ 1, c + 1);
            CP_WAIT1();
        } else CP_WAIT0();
        __syncthreads();
#pragma unroll
        for (int ks = 0; ks < 2; ks++) {
            const int kb = ks * 16;
            uint32_t af[2][4];
#pragma unroll
            for (int i = 0; i < 2; i++) {
                int row = wm * 32 + i * 16 + (lane & 7) + ((lane >> 3) & 1) * 8;
                int col = kb + ((lane >> 4) & 1) * 8;
                LDM_X4(af[i][0], af[i][1], af[i][2], af[i][3],
                       sA + (uint32_t)(buf * (MT * 80) + row * 80 + col * 2));
            }
            uint32_t bfr[NJ][2];
#pragma unroll
            for (int jp = 0; jp < NJ / 2; jp++) {
                int n = wn * (NJ * 8) + jp * 16 + (lane & 7) + ((lane >> 4) & 1) * 8;
                int k = kb + ((lane >> 3) & 1) * 8;
                LDM_X4(bfr[2 * jp][0], bfr[2 * jp][1],
                       bfr[2 * jp + 1][0], bfr[2 * jp + 1][1],
                       sB + (uint32_t)(buf * 10240 + n * 80 + k * 2));
            }
#pragma unroll
            for (int i = 0; i < 2; i++)
#pragma unroll
                for (int j = 0; j < NJ; j++)
                    MMA16816(acc[i][j], af[i], bfr[j]);
        }
        __syncthreads();
    }

    float* Ob = out + (long long)b * out_bstride;
#pragma unroll
    for (int i = 0; i < 2; i++)
#pragma unroll
        for (int h = 0; h < 2; h++) {
            int m = wm * 32 + i * 16 + (lane >> 2) + h * 8;
            float bi = bias[m];
            float sc = scale ? scale[m] : 1.f;
            float ofv = off ? off[m] : 0.f;
            float* crow = Ob + (long long)m * 4096;
#pragma unroll
            for (int j = 0; j < NJ; j++) {
                int col = n0 + wn * (NJ * 8) + j * 8 + (lane & 3) * 2;
                float2 v = make_float2(acc[i][j][h * 2 + 0] + bi,
                                       acc[i][j][h * 2 + 1] + bi);
                if (scale) {
                    v.x = fmaxf(v.x, 0.f) * sc + ofv;
                    v.y = fmaxf(v.y, 0.f) * sc + ofv;
                }
                *(float2*)(crow + col) = v;
            }
        }
}

// ===========================================================================
// prep kernels
// ===========================================================================
// weight split: src f32 [M,K] -> dst bf16 [M,3K] pattern A (hi,lo,hi)
__global__ void wsplit_k(const float* __restrict__ src, __nv_bfloat16* __restrict__ dst,
                         int K, int total)
{
    int i = blockIdx.x * 256 + threadIdx.x;
    if (i >= total) return;
    int m = i / K, k = i - m * K;
    __nv_bfloat16 h, l; bsplit(src[i], h, l);
    __nv_bfloat16* o = dst + (long long)m * 3 * K + k;
    o[0] = h; o[K] = l; o[2 * K] = h;
}

// transpose+split: in [B,R,Ncol] f32 -> out [B,Ncol,3R] bf16.
// patB==0: (hi,lo,hi) [A operand]; patB==1: (hi,hi,lo) [B operand]
__global__ void tsplit3_k(const float* __restrict__ in, __nv_bfloat16* __restrict__ out,
                          int R, int Ncol, int patB)
{
    __shared__ float tile[32][33];
    const int b = blockIdx.z, r0 = blockIdx.y * 32, n0 = blockIdx.x * 32;
    const int tx = threadIdx.x & 31, ty = threadIdx.x >> 5;
    const float* ib = in + (long long)b * R * Ncol;
#pragma unroll
    for (int p = 0; p < 4; p++)
        tile[ty + 8 * p][tx] = ib[(long long)(r0 + ty + 8 * p) * Ncol + n0 + tx];
    __syncthreads();
    __nv_bfloat16* ob = out + (long long)b * Ncol * 3 * R;
#pragma unroll
    for (int p = 0; p < 4; p++) {
        int n = n0 + ty + 8 * p, r = r0 + tx;
        float x = tile[tx][ty + 8 * p];
        __nv_bfloat16 h, l; bsplit(x, h, l);
        __nv_bfloat16* o = ob + (long long)n * 3 * R;
        if (patB) { o[r] = h; o[R + r] = h; o[2 * R + r] = l; }
        else      { o[r] = h; o[R + r] = l; o[2 * R + r] = h; }
    }
}

// attn3: simp [B*1024,128] f32 -> [B,1024,384] bf16, pattern B
__global__ void split3row_k(const float* __restrict__ in, __nv_bfloat16* __restrict__ out)
{
    int i = blockIdx.x * 256 + threadIdx.x;
    float x = in[i];
    __nv_bfloat16 h, l; bsplit(x, h, l);
    long long row = i >> 7; int c = i & 127;
    __nv_bfloat16* o = out + row * 384 + c;
    o[0] = h; o[128] = h; o[256] = l;
}

// column softmax stats over logitsT [B,4096,1024]
__global__ void colstat_k(const float* __restrict__ lt,
                          float* __restrict__ cmax, float* __restrict__ csum)
{
    __shared__ float smx[16][65], ssm[16][65];
    const int b = blockIdx.y;
    const int c = threadIdx.x & 63, g = threadIdx.x >> 6;
    const int col = blockIdx.x * 64 + c;
    const float* p = lt + (long long)b * 4194304 + col;
    float mx = -1e30f, sm = 0.f;
    for (int m = g; m < 4096; m += 16) {
        float x = p[(long long)m * 1024];
        float nm = fmaxf(mx, x);
        sm = sm * __expf(mx - nm) + __expf(x - nm);
        mx = nm;
    }
    smx[g][c] = mx; ssm[g][c] = sm;
    __syncthreads();
    if (g == 0) {
        float MX = smx[0][c], SM = ssm[0][c];
#pragma unroll
        for (int k = 1; k < 16; k++) {
            float m2 = smx[k][c], s2 = ssm[k][c];
            float nm = fmaxf(MX, m2);
            SM = SM * __expf(MX - nm) + s2 * __expf(m2 - nm);
            MX = nm;
        }
        cmax[b * 1024 + col] = MX;
        csum[b * 1024 + col] = 1.f / SM;
    }
}

// normalize + split -> aT3 [B,4096,3072], pattern B
__global__ void colwrite_k(const float* __restrict__ lt,
                           const float* __restrict__ cmax, const float* __restrict__ csum,
                           __nv_bfloat16* __restrict__ out)
{
    long long i = (long long)blockIdx.x * 256 + threadIdx.x;
    int tcol = (int)(i & 1023);
    long long bm = i >> 10;
    int b = (int)(bm >> 12);
    float e = __expf(lt[i] - cmax[b * 1024 + tcol]) * csum[b * 1024 + tcol];
    __nv_bfloat16 h, l; bsplit(e, h, l);
    __nv_bfloat16* o = out + bm * 3072 + tcol;
    o[0] = h; o[1024] = h; o[2048] = l;
}

// ===========================================================================
// scalar auxiliary kernels
// ===========================================================================
__global__ void cos_k(const float* __restrict__ r1, const float* __restrict__ r2,
                      float* __restrict__ sim)
{
    int gid  = blockIdx.x * blockDim.x + threadIdx.x;
    int wid  = gid >> 5;
    int lane = gid & 31;
    if (wid >= 4 * 4096) return;
    const float* a = r1 + (long long)wid * 128;
    const float* c = r2 + (long long)wid * 128;
    float dot = 0.f, na = 0.f, nb = 0.f;
#pragma unroll
    for (int i = 0; i < 4; i++) {
        float x = a[lane + 32 * i], y = c[lane + 32 * i];
        dot += x * y; na += x * x; nb += y * y;
    }
#pragma unroll
    for (int o = 16; o; o >>= 1) {
        dot += __shfl_xor_sync(0xffffffffu, dot, o);
        na  += __shfl_xor_sync(0xffffffffu, na,  o);
        nb  += __shfl_xor_sync(0xffffffffu, nb,  o);
    }
    if (lane == 0)
        sim[wid] = dot / fmaxf(sqrtf(na) * sqrtf(nb), 1e-8f);
}

__global__ void difsim_k(const float* __restrict__ r1, const float* __restrict__ r2,
                         const float* __restrict__ sim,
                         float* __restrict__ difcat, float* __restrict__ absd)
{
    __shared__ float f1s[32][33], f2s[32][33], ss[32];
    const int b  = blockIdx.z;
    const int c0 = blockIdx.y * 32;
    const int n0 = blockIdx.x * 32;
    const int t  = threadIdx.x;
    const int tx = t & 31, ty = t >> 5;
    const long long BS = 524288;
    const float* r1b = r1 + (long long)b * BS;
    const float* r2b = r2 + (long long)b * BS;
#pragma unroll
    for (int r = 0; r < 4; r++) {
        int n = ty + 8 * r;
        f1s[n][tx] = r1b[(long long)(n0 + n) * 128 + c0 + tx];
        f2s[n][tx] = r2b[(long long)(n0 + n) * 128 + c0 + tx];
    }
    if (t < 32) ss[t] = sim[b * 4096 + n0 + t];
    __syncthreads();
#pragma unroll
    for (int r = 0; r < 4; r++) {
        int c = c0 + ty + 8 * r;
        int n = n0 + tx;
        float rv1 = r1b[(long long)c * 4096 + n];
        float rv2 = r2b[(long long)c * 4096 + n];
        float s  = ss[tx];
        float f1 = f1s[tx][ty + 8 * r];
        float f2 = f2s[tx][ty + 8 * r];
        float omns = 1.f - s;
        long long bo = (long long)b * (256LL * 4096) + (long long)c * 4096 + n;
        difcat[bo]                = f1 * omns + rv1;
        difcat[bo + 128LL * 4096] = f2 * omns + rv2;
        absd[(long long)b * BS + (long long)c * 4096 + n] =
            fabsf((f1 - f2) * s + rv1 - rv2);
    }
}

__global__ void pool_k(const float* __restrict__ absd, float* __restrict__ simp)
{
    int i = blockIdx.x * 256 + threadIdx.x;
    if (i >= 524288) return;
    int wp = i & 31, hp = (i >> 5) & 31, bc = i >> 10;
    const float* a = absd + (long long)bc * 4096 + (hp * 2) * 64 + wp * 2;
    simp[i] = 0.25f * (a[0] + a[1] + a[64] + a[65]);
}

__global__ void resize_k(const float* __restrict__ in, float* __restrict__ out)
{
    long long i = (long long)blockIdx.x * 256 + threadIdx.x;
    if (i >= 8388608LL) return;
    int x = (int)(i & 127), y = (int)((i >> 7) & 127);
    long long bc = i >> 14;
    float sx = (x + 0.5f) * 0.5f - 0.5f;
    float sy = (y + 0.5f) * 0.5f - 0.5f;
    int x0 = (int)floorf(sx), y0 = (int)floorf(sy);
    float fx = sx - x0, fy = sy - y0;
    int x1 = min(x0 + 1, 63), y1 = min(y0 + 1, 63);
    x0 = max(x0, 0); y0 = max(y0, 0);
    const float* p = in + bc * 4096;
    float v = (1.f - fy) * ((1.f - fx) * p[y0 * 64 + x0] + fx * p[y0 * 64 + x1])
            +        fy  * ((1.f - fx) * p[y1 * 64 + x0] + fx * p[y1 * 64 + x1]);
    out[i] = v;
}

// ---------------------------------------------------------------------------
extern "C" void kernel_launch(void* const* d_in, const int* in_sizes, int n_in,
                              void* d_out, int out_size)
{
    (void)in_sizes; (void)n_in; (void)out_size;
    const float* t1      = (const float*)d_in[0];
    const float* t2      = (const float*)d_in[1];
    const float* t1_w    = (const float*)d_in[2];
    const float* t1_b    = (const float*)d_in[3];
    const float* t2_w    = (const float*)d_in[4];
    const float* t2_b    = (const float*)d_in[5];
    const float* df_res_w = (const float*)d_in[6];
    const float* df_res_b = (const float*)d_in[7];
    const float* df_res_s = (const float*)d_in[8];
    const float* df_res_o = (const float*)d_in[9];
    const float* df_b0_w = (const float*)d_in[10];
    const float* df_b0_b = (const float*)d_in[11];
    const float* df_b0_s = (const float*)d_in[12];
    const float* df_b0_o = (const float*)d_in[13];
    const float* df_b1_w = (const float*)d_in[14];
    const float* df_b1_b = (const float*)d_in[15];
    const float* df_b1_s = (const float*)d_in[16];
    const float* df_b1_o = (const float*)d_in[17];
    const float* df_fu_w = (const float*)d_in[18];
    const float* df_fu_b = (const float*)d_in[19];
    const float* df_fu_s = (const float*)d_in[20];
    const float* df_fu_o = (const float*)d_in[21];
    const float* br1_w   = (const float*)d_in[22];
    const float* br1_b   = (const float*)d_in[23];
    const float* br2_w   = (const float*)d_in[24];
    const float* br2_b   = (const float*)d_in[25];
    const float* fu_w    = (const float*)d_in[26];
    const float* fu_b    = (const float*)d_in[27];
    const float* fu_s    = (const float*)d_in[28];
    const float* fu_o    = (const float*)d_in[29];
    float* out = (float*)d_out;

    float* S;
    cudaGetSymbolAddress((void**)&S, g_scratch);
    __nv_bfloat16* G;
    cudaGetSymbolAddress((void**)&G, g_bf);

    float* res1    = S + F_RES1;
    float* res2    = S + F_RES2;
    float* sim     = S + F_SIM;
    float* difcat  = S + F_DIFC;
    float* absd    = S + F_ABSD;
    float* simp    = S + F_SIMP;
    float* rbuf    = S + F_R;
    float* b0b1    = S + F_B0B1;
    float* dif     = S + F_DIF;
    float* inc     = S + F_INC;
    float* logitsT = S + F_LOG;
    float* acat    = S + F_ACAT;
    float* fuse    = S + F_FUSE;
    float* cmax    = S + F_PAR;
    float* csum    = S + F_PAR + 4096;

    const long long S128 = 128LL * 4096;
    const long long S256 = 256LL * 4096;

    // ---- weight splits (tiny) ----
    wsplit_k<<<128, 256>>>(t1_w,    G + W_T1W3,   256, 32768);
    wsplit_k<<<128, 256>>>(t2_w,    G + W_T2W3,   256, 32768);
    wsplit_k<<<128, 256>>>(df_res_w,G + W_RESW3,  256, 32768);
    wsplit_k<<<128, 256>>>(fu_w,    G + W_FUW3,   256, 32768);
    wsplit_k<<<64,  256>>>(df_fu_w, G + W_DFUW3,  128, 16384);
    wsplit_k<<<288, 256>>>(df_b0_w, G + W_B0W3,   1152, 73728);
    wsplit_k<<<800, 256>>>(df_b1_w, G + W_B1W3,   3200, 204800);
    wsplit_k<<<576, 256>>>(br1_w,   G + W_BR1W3,  1152, 147456);
    wsplit_k<<<1600,256>>>(br2_w,   G + W_BR2W3,  3200, 409600);

    // 1. res1/res2 = 1x1 (256->128) + bias
    tsplit3_k<<<dim3(128, 8, 4), 256>>>(t1, G + G_T3A, 256, 4096, 1);
    tsplit3_k<<<dim3(128, 8, 4), 256>>>(t2, G + G_T3B, 256, 4096, 1);
    hmma_gemm<<<dim3(32, 1, 4), 256>>>(G + W_T1W3, G + G_T3A, res1,
                                       t1_b, nullptr, nullptr, nullptr,
                                       768, 4096, 0, 4096LL * 768, S128, 0);
    hmma_gemm<<<dim3(32, 1, 4), 256>>>(G + W_T2W3, G + G_T3B, res2,
                                       t2_b, nullptr, nullptr, nullptr,
                                       768, 4096, 0, 4096LL * 768, S128, 0);
    // 2-4. cosine, dif mixing, avgpool; attention static operands
    cos_k<<<2048, 256>>>(res1, res2, sim);
    difsim_k<<<dim3(128, 4, 4), 256>>>(res1, res2, sim, difcat, absd);
    pool_k<<<2048, 256>>>(absd, simp);
    split3row_k<<<2048, 256>>>(simp, G + G_ATTN3);
    tsplit3_k<<<dim3(4, 32, 4), 256>>>(simp, G + G_ATTNT3, 1024, 128, 0);
    // 5. r = stdconv 1x1 (256->128)
    tsplit3_k<<<dim3(128, 8, 4), 256>>>(difcat, G + G_T3A, 256, 4096, 1);
    hmma_gemm<<<dim3(32, 1, 4), 256>>>(G + W_RESW3, G + G_T3A, rbuf,
                                       df_res_b, df_res_s, df_res_o, nullptr,
                                       768, 4096, 0, 4096LL * 768, S128, 0);
    // 6/7. inception branches (3x3 and 5x5, 128->64 each)
    hconv<3, 64><<<dim3(32, 1, 4), 256>>>(rbuf, G + W_B0W3, b0b1,
                                          df_b0_b, df_b0_s, df_b0_o, S128);
    hconv<5, 64><<<dim3(32, 1, 4), 256>>>(rbuf, G + W_B1W3, b0b1 + 64LL * 4096,
                                          df_b1_b, df_b1_s, df_b1_o, S128);
    // 8. dif = stdconv 1x1 (128->128) + r
    tsplit3_k<<<dim3(128, 4, 4), 256>>>(b0b1, G + G_BBT3, 128, 4096, 1);
    hmma_gemm<<<dim3(32, 1, 4), 256>>>(G + W_DFUW3, G + G_BBT3, dif,
                                       df_fu_b, df_fu_s, df_fu_o, rbuf,
                                       384, 4096, 0, 4096LL * 384, S128, S128);
    // --- attention branches ---
    for (int br = 0; br < 2; br++) {
        if (br == 0)
            hconv<3, 128><<<dim3(32, 1, 4), 256>>>(dif, G + W_BR1W3, inc,
                                                   br1_b, nullptr, nullptr, S128);
        else
            hconv<5, 128><<<dim3(32, 1, 4), 256>>>(dif, G + W_BR2W3, inc,
                                                   br2_b, nullptr, nullptr, S128);
        tsplit3_k<<<dim3(128, 4, 4), 256>>>(inc, G + G_INCT3, 128, 4096, 0);
        // logitsT[b, pix, tok] = incT . attn
        hmma_gemm<<<dim3(8, 32, 4), 256>>>(G + G_INCT3, G + G_ATTN3, logitsT,
                                           nullptr, nullptr, nullptr, nullptr,
                                           384, 1024,
                                           4096LL * 384, 1024LL * 384,
                                           4096LL * 1024, 0);
        colstat_k<<<dim3(16, 4), 1024>>>(logitsT, cmax, csum);
        colwrite_k<<<65536, 256>>>(logitsT, cmax, csum, G + G_AT3);
        // out[b, c, pix] = attnT . aT + inc  -> acat half
        hmma_gemm<<<dim3(32, 1, 4), 256>>>(G + G_ATTNT3, G + G_AT3,
                                           acat + (long long)br * S128,
                                           nullptr, nullptr, nullptr, inc,
                                           3072, 4096,
                                           128LL * 3072, 4096LL * 3072,
                                           S256, S128);
    }
    // 14. fused = stdconv 1x1 (256->128) + dif
    tsplit3_k<<<dim3(128, 8, 4), 256>>>(acat, G + G_T3A, 256, 4096, 1);
    hmma_gemm<<<dim3(32, 1, 4), 256>>>(G + W_FUW3, G + G_T3A, fuse,
                                       fu_b, fu_s, fu_o, dif,
                                       768, 4096, 0, 4096LL * 768, S128, S128);
    // 15. bilinear x2 upsample
    resize_k<<<32768, 256>>>(fuse, out);
}

// round 8
// speedup vs baseline: 2.1647x; 2.1647x over previous
#include <cuda_runtime.h>
#include <cuda_bf16.h>
#include <cstdint>

// ===========================================================================
// B=4, C_IN=256, C=128, H=W=64, HW=4096. out [4,128,128,128] f32.
// ALL dense ops on mma.sync bf16 HMMA, 2-term split (K'=3K):
//   A (hi,lo,hi) x B (hi,hi,lo) => Ahi.Bhi + Alo.Bhi + Ahi.Blo (err ~2^-18)
// Convs = sum of per-tap shifted GEMMs over the L2-resident split input
// (cp.async zfill handles borders). 3-stage cp.async pipeline everywhere.
// ===========================================================================

#define F_RES1 0LL
#define F_RES2 (F_RES1 + 2097152)
#define F_SIM  (F_RES2 + 2097152)
#define F_DIFC (F_SIM  + 16384)
#define F_ABSD (F_DIFC + 4194304)
#define F_SIMP (F_ABSD + 2097152)
#define F_R    (F_SIMP + 524288)
#define F_B0B1 (F_R    + 2097152)
#define F_DIF  (F_B0B1 + 2097152)
#define F_INC  (F_DIF  + 2097152)
#define F_LOG  (F_INC  + 2097152)      /* logitsT [B,4096,1024] */
#define F_ACAT (F_LOG  + 16777216)
#define F_FUSE (F_ACAT + 4194304)
#define F_PAR  (F_FUSE + 2097152)
#define F_TOTAL (F_PAR + 8192)

__device__ float g_scratch[F_TOTAL];

// bf16 scratch element offsets
#define W_T1W3   0LL         /* [128,768]        */
#define W_T2W3   98304LL
#define W_RESW3  196608LL
#define W_FUW3   294912LL
#define W_DFUW3  393216LL    /* [128,384]        */
#define W_B0T    442368LL    /* [9][64][384]     */
#define W_B1T    663552LL    /* [25][64][384]    */
#define W_BR1T   1277952LL   /* [9][128][384]    */
#define W_BR2T   1720320LL   /* [25][128][384]   */
#define G_ATTN3  2949120LL   /* [4,1024,384]     */
#define G_INCT3  4521984LL   /* [4,4096,384]     */
#define G_ATTNT3 10813440LL  /* [4,128,3072]     */
#define G_AT3    12386304LL  /* [4,4096,3072]    */
#define G_T3A    62717952LL  /* [4,4096,768]     */
#define G_T3B    75300864LL  /* [4,4096,768]     */
#define G_RB3    87883776LL  /* [4,4096,384]     */
#define G_DIF3   94175232LL  /* [4,4096,384]     */
#define G_BB3    100466688LL /* [4,4096,384]     */
#define G_TOTAL  106758144LL

__device__ __align__(256) __nv_bfloat16 g_bf[G_TOTAL];

// ------------------------------ helpers ------------------------------------
__device__ __forceinline__ uint32_t smem_u32(const void* p) {
    uint32_t a;
    asm("{ .reg .u64 t; cvta.to.shared.u64 t, %1; cvt.u32.u64 %0, t; }"
        : "=r"(a) : "l"(p));
    return a;
}
__device__ __forceinline__ void bsplit(float x, __nv_bfloat16& h, __nv_bfloat16& l) {
    h = __float2bfloat16(x);
    l = __float2bfloat16(x - __bfloat162float(h));
}
#define CP_ASYNC(dst, src) asm volatile( \
    "cp.async.cg.shared.global [%0], [%1], 16;" :: "r"(dst), "l"(src))
#define CP_ASYNC_Z(dst, src, sz) asm volatile( \
    "cp.async.cg.shared.global [%0], [%1], 16, %2;" :: "r"(dst), "l"(src), "r"(sz))
#define CP_COMMIT() asm volatile("cp.async.commit_group;" ::: "memory")
#define CP_WAIT1()  asm volatile("cp.async.wait_group 1;" ::: "memory")
#define CP_WAIT0()  asm volatile("cp.async.wait_group 0;" ::: "memory")
#define LDM_X4(r0, r1, r2, r3, a) asm volatile( \
    "ldmatrix.sync.aligned.m8n8.x4.shared.b16 {%0,%1,%2,%3}, [%4];" \
    : "=r"(r0), "=r"(r1), "=r"(r2), "=r"(r3) : "r"(a))
#define MMA16816(d, a, bfr) asm volatile( \
    "mma.sync.aligned.m16n8k16.row.col.f32.bf16.bf16.f32 " \
    "{%0,%1,%2,%3}, {%4,%5,%6,%7}, {%8,%9}, {%0,%1,%2,%3};" \
    : "+f"((d)[0]), "+f"((d)[1]), "+f"((d)[2]), "+f"((d)[3]) \
    : "r"((a)[0]), "r"((a)[1]), "r"((a)[2]), "r"((a)[3]), \
      "r"((bfr)[0]), "r"((bfr)[1]))

// ===========================================================================
// hmma_gemm: 128x128 tile, 8 warps (32m x 64n), chunk k=32, 3-stage cp.async.
// C[b,m,n] = sum_k A3[m,k]*B3[n,k] (+bias, relu-affine, resid)
// A3 [Mtot,Kp], B3 [Ntot,Kp] bf16 row-major; Kp % 32 == 0.
// dyn smem = 61440. grid = (N/128, M/128, B).
// ===========================================================================
__global__ void __launch_bounds__(256) hmma_gemm(
    const __nv_bfloat16* __restrict__ A3, const __nv_bfloat16* __restrict__ B3,
    float* __restrict__ C,
    const float* __restrict__ bias, const float* __restrict__ scale,
    const float* __restrict__ off, const float* __restrict__ resid,
    int Kp, int Ncols,
    long long Abs, long long Bbs, long long Cbs, long long Rbs)
{
    extern __shared__ __align__(16) char smbuf[];
    const uint32_t sA = smem_u32(smbuf);          // 3 stages x 10240
    const uint32_t sB = sA + 30720;               // 3 stages x 10240
    const int t = threadIdx.x, lane = t & 31, wid = t >> 5;
    const int wm = wid & 3, wn = wid >> 2;
    const int b  = blockIdx.z;
    const int m0 = blockIdx.y * 128;
    const int n0 = blockIdx.x * 128;
    const __nv_bfloat16* Ab = A3 + (long long)b * Abs + (long long)m0 * Kp;
    const __nv_bfloat16* Bb = B3 + (long long)b * Bbs + (long long)n0 * Kp;

    float acc[2][8][4];
#pragma unroll
    for (int i = 0; i < 2; i++)
#pragma unroll
        for (int j = 0; j < 8; j++)
#pragma unroll
            for (int r = 0; r < 4; r++) acc[i][j][r] = 0.f;

    auto ldch = [&](int c) {
        const uint32_t ao = sA + (c % 3) * 10240;
        const uint32_t bo = sB + (c % 3) * 10240;
#pragma unroll
        for (int r = 0; r < 2; r++) {
            int f = t + 256 * r, row = f >> 2, kq = f & 3;
            CP_ASYNC(ao + (uint32_t)(row * 80 + kq * 16),
                     Ab + (long long)row * Kp + c * 32 + kq * 8);
            CP_ASYNC(bo + (uint32_t)(row * 80 + kq * 16),
                     Bb + (long long)row * Kp + c * 32 + kq * 8);
        }
        CP_COMMIT();
    };

    const int nch = Kp >> 5;
    ldch(0);
    if (nch > 1) ldch(1);
    for (int c = 0; c < nch; c++) {
        if (c + 1 < nch) CP_WAIT1(); else CP_WAIT0();
        __syncthreads();
        if (c + 2 < nch) ldch(c + 2);
        const uint32_t ao = sA + (c % 3) * 10240;
        const uint32_t bo = sB + (c % 3) * 10240;
#pragma unroll
        for (int ks = 0; ks < 2; ks++) {
            const int kb = ks * 16;
            uint32_t af[2][4];
#pragma unroll
            for (int i = 0; i < 2; i++) {
                int row = wm * 32 + i * 16 + (lane & 7) + ((lane >> 3) & 1) * 8;
                int col = kb + ((lane >> 4) & 1) * 8;
                LDM_X4(af[i][0], af[i][1], af[i][2], af[i][3],
                       ao + (uint32_t)(row * 80 + col * 2));
            }
            uint32_t bfr[8][2];
#pragma unroll
            for (int jp = 0; jp < 4; jp++) {
                int n = wn * 64 + jp * 16 + (lane & 7) + ((lane >> 4) & 1) * 8;
                int k = kb + ((lane >> 3) & 1) * 8;
                LDM_X4(bfr[2 * jp][0], bfr[2 * jp][1],
                       bfr[2 * jp + 1][0], bfr[2 * jp + 1][1],
                       bo + (uint32_t)(n * 80 + k * 2));
            }
#pragma unroll
            for (int i = 0; i < 2; i++)
#pragma unroll
                for (int j = 0; j < 8; j++)
                    MMA16816(acc[i][j], af[i], bfr[j]);
        }
        __syncthreads();
    }

    float* Cb = C + (long long)b * Cbs;
    const float* Rb = resid ? resid + (long long)b * Rbs : nullptr;
#pragma unroll
    for (int i = 0; i < 2; i++)
#pragma unroll
        for (int h = 0; h < 2; h++) {
            int m = m0 + wm * 32 + i * 16 + (lane >> 2) + h * 8;
            float bi = bias  ? bias[m]  : 0.f;
            float sc = scale ? scale[m] : 1.f;
            float ofv = off  ? off[m]   : 0.f;
            float* crow = Cb + (long long)m * Ncols;
            const float* rrow = Rb ? Rb + (long long)m * Ncols : nullptr;
#pragma unroll
            for (int j = 0; j < 8; j++) {
                int col = n0 + wn * 64 + j * 8 + (lane & 3) * 2;
                float2 v = make_float2(acc[i][j][h * 2 + 0] + bi,
                                       acc[i][j][h * 2 + 1] + bi);
                if (scale) {
                    v.x = fmaxf(v.x, 0.f) * sc + ofv;
                    v.y = fmaxf(v.y, 0.f) * sc + ofv;
                }
                if (rrow) {
                    float2 rv = *(const float2*)(rrow + col);
                    v.x += rv.x; v.y += rv.y;
                }
                *(float2*)(crow + col) = v;
            }
        }
}

// ===========================================================================
// hconv_tap: conv KSxKS (pad KS/2) as sum of per-tap shifted GEMMs.
// W3t [tap][MT][384] bf16 (hi,lo,hi); Bsplit [B][4096][384] bf16 (hi,hi,lo).
// MT in {64,128}. grid = (32, 1, B). dyn smem = 3*(MT*80) + 30720.
// ===========================================================================
template <int KS, int MT>
__global__ void __launch_bounds__(256) hconv_tap(
    const __nv_bfloat16* __restrict__ W3t, const __nv_bfloat16* __restrict__ Bsplit,
    float* __restrict__ out,
    const float* __restrict__ bias, const float* __restrict__ scale,
    const float* __restrict__ off, long long out_bstride)
{
    constexpr int P    = KS / 2;
    constexpr int TAPS = KS * KS;
    constexpr int NC   = TAPS * 12;          // total k-chunks (384/32 per tap)
    constexpr int WM_N = MT / 32;
    constexpr int WN_N = 8 / WM_N;
    constexpr int NJ   = 128 / (WN_N * 8);
    constexpr int ASTG = MT * 80;
    extern __shared__ __align__(16) char smbuf[];
    const uint32_t sA = smem_u32(smbuf);        // 3 x ASTG
    const uint32_t sB = sA + 3 * ASTG;          // 3 x 10240
    const int t = threadIdx.x, lane = t & 31, wid = t >> 5;
    const int wm = wid % WM_N, wn = wid / WM_N;
    const int b  = blockIdx.z;
    const int n0 = blockIdx.x * 128;
    const __nv_bfloat16* Bb = Bsplit + (long long)b * (4096LL * 384);

    float acc[2][NJ][4];
#pragma unroll
    for (int i = 0; i < 2; i++)
#pragma unroll
        for (int j = 0; j < NJ; j++)
#pragma unroll
            for (int r = 0; r < 4; r++) acc[i][j][r] = 0.f;

    auto ldch = [&](int gc) {
        const int tap = gc / 12;
        const int c   = gc - tap * 12;
        const int dy  = tap / KS - P, dx = tap - (tap / KS) * KS - P;
        const int shift = dy * 64 + dx;
        const uint32_t ao = sA + (gc % 3) * ASTG;
        const uint32_t bo = sB + (gc % 3) * 10240;
#pragma unroll
        for (int r = 0; r < MT / 64; r++) {
            int f = t + 256 * r, row = f >> 2, kq = f & 3;
            CP_ASYNC(ao + (uint32_t)(row * 80 + kq * 16),
                     W3t + (long long)tap * (MT * 384) + (long long)row * 384
                         + c * 32 + kq * 8);
        }
#pragma unroll
        for (int r = 0; r < 2; r++) {
            int f = t + 256 * r, row = f >> 2, kq = f & 3;
            int gpix = n0 + row;
            int y = gpix >> 6, x = gpix & 63;
            bool ok = ((unsigned)(y + dy) < 64u) && ((unsigned)(x + dx) < 64u);
            int spix = ok ? (gpix + shift) : 0;
            uint32_t sz = ok ? 16u : 0u;
            CP_ASYNC_Z(bo + (uint32_t)(row * 80 + kq * 16),
                       Bb + (long long)spix * 384 + c * 32 + kq * 8, sz);
        }
        CP_COMMIT();
    };

    ldch(0);
    ldch(1);
    for (int gc = 0; gc < NC; gc++) {
        if (gc + 1 < NC) CP_WAIT1(); else CP_WAIT0();
        __syncthreads();
        if (gc + 2 < NC) ldch(gc + 2);
        const uint32_t ao = sA + (gc % 3) * ASTG;
        const uint32_t bo = sB + (gc % 3) * 10240;
#pragma unroll
        for (int ks = 0; ks < 2; ks++) {
            const int kb = ks * 16;
            uint32_t af[2][4];
#pragma unroll
            for (int i = 0; i < 2; i++) {
                int row = wm * 32 + i * 16 + (lane & 7) + ((lane >> 3) & 1) * 8;
                int col = kb + ((lane >> 4) & 1) * 8;
                LDM_X4(af[i][0], af[i][1], af[i][2], af[i][3],
                       ao + (uint32_t)(row * 80 + col * 2));
            }
            uint32_t bfr[NJ][2];
#pragma unroll
            for (int jp = 0; jp < NJ / 2; jp++) {
                int n = wn * (NJ * 8) + jp * 16 + (lane & 7) + ((lane >> 4) & 1) * 8;
                int k = kb + ((lane >> 3) & 1) * 8;
                LDM_X4(bfr[2 * jp][0], bfr[2 * jp][1],
                       bfr[2 * jp + 1][0], bfr[2 * jp + 1][1],
                       bo + (uint32_t)(n * 80 + k * 2));
            }
#pragma unroll
            for (int i = 0; i < 2; i++)
#pragma unroll
                for (int j = 0; j < NJ; j++)
                    MMA16816(acc[i][j], af[i], bfr[j]);
        }
        __syncthreads();
    }

    float* Ob = out + (long long)b * out_bstride;
#pragma unroll
    for (int i = 0; i < 2; i++)
#pragma unroll
        for (int h = 0; h < 2; h++) {
            int m = wm * 32 + i * 16 + (lane >> 2) + h * 8;
            float bi = bias[m];
            float sc = scale ? scale[m] : 1.f;
            float ofv = off ? off[m] : 0.f;
            float* crow = Ob + (long long)m * 4096;
#pragma unroll
            for (int j = 0; j < NJ; j++) {
                int col = n0 + wn * (NJ * 8) + j * 8 + (lane & 3) * 2;
                float2 v = make_float2(acc[i][j][h * 2 + 0] + bi,
                                       acc[i][j][h * 2 + 1] + bi);
                if (scale) {
                    v.x = fmaxf(v.x, 0.f) * sc + ofv;
                    v.y = fmaxf(v.y, 0.f) * sc + ofv;
                }
                *(float2*)(crow + col) = v;
            }
        }
}

// ===========================================================================
// prep kernels
// ===========================================================================
// 1x1 weight split: src f32 [M,K] -> dst bf16 [M,3K] pattern A (hi,lo,hi)
__global__ void wsplit_k(const float* __restrict__ src, __nv_bfloat16* __restrict__ dst,
                         int K, int total)
{
    int i = blockIdx.x * 256 + threadIdx.x;
    if (i >= total) return;
    int m = i / K, k = i - m * K;
    __nv_bfloat16 h, l; bsplit(src[i], h, l);
    __nv_bfloat16* o = dst + (long long)m * 3 * K + k;
    o[0] = h; o[K] = l; o[2 * K] = h;
}

// conv weight split: src OIHW f32 [Cout,128,KS2] -> dst [tap][Cout][384] (hi,lo,hi)
__global__ void wsplit_tap_k(const float* __restrict__ src, __nv_bfloat16* __restrict__ dst,
                             int Cout, int KS2, int total)
{
    int i = blockIdx.x * 256 + threadIdx.x;
    if (i >= total) return;
    int co = i / (128 * KS2);
    int rem = i - co * 128 * KS2;
    int ci = rem / KS2;
    int tap = rem - ci * KS2;
    __nv_bfloat16 h, l; bsplit(src[i], h, l);
    __nv_bfloat16* o = dst + (long long)tap * Cout * 384 + (long long)co * 384 + ci;
    o[0] = h; o[128] = l; o[256] = h;
}

// transpose+split: in [B,R,Ncol] f32 -> out [B,Ncol,3R] bf16.
// patB==0: (hi,lo,hi); patB==1: (hi,hi,lo)
__global__ void tsplit3_k(const float* __restrict__ in, __nv_bfloat16* __restrict__ out,
                          int R, int Ncol, int patB)
{
    __shared__ float tile[32][33];
    const int b = blockIdx.z, r0 = blockIdx.y * 32, n0 = blockIdx.x * 32;
    const int tx = threadIdx.x & 31, ty = threadIdx.x >> 5;
    const float* ib = in + (long long)b * R * Ncol;
#pragma unroll
    for (int p = 0; p < 4; p++)
        tile[ty + 8 * p][tx] = ib[(long long)(r0 + ty + 8 * p) * Ncol + n0 + tx];
    __syncthreads();
    __nv_bfloat16* ob = out + (long long)b * Ncol * 3 * R;
#pragma unroll
    for (int p = 0; p < 4; p++) {
        int n = n0 + ty + 8 * p, r = r0 + tx;
        float x = tile[tx][ty + 8 * p];
        __nv_bfloat16 h, l; bsplit(x, h, l);
        __nv_bfloat16* o = ob + (long long)n * 3 * R;
        if (patB) { o[r] = h; o[R + r] = h; o[2 * R + r] = l; }
        else      { o[r] = h; o[R + r] = l; o[2 * R + r] = h; }
    }
}

// attn3: simp [B*1024,128] f32 -> [B,1024,384] bf16, pattern B
__global__ void split3row_k(const float* __restrict__ in, __nv_bfloat16* __restrict__ out)
{
    int i = blockIdx.x * 256 + threadIdx.x;
    float x = in[i];
    __nv_bfloat16 h, l; bsplit(x, h, l);
    long long row = i >> 7; int c = i & 127;
    __nv_bfloat16* o = out + row * 384 + c;
    o[0] = h; o[128] = h; o[256] = l;
}

// column softmax stats over logitsT [B,4096,1024]
__global__ void colstat_k(const float* __restrict__ lt,
                          float* __restrict__ cmax, float* __restrict__ csum)
{
    __shared__ float smx[16][65], ssm[16][65];
    const int b = blockIdx.y;
    const int c = threadIdx.x & 63, g = threadIdx.x >> 6;
    const int col = blockIdx.x * 64 + c;
    const float* p = lt + (long long)b * 4194304 + col;
    float mx = -1e30f, sm = 0.f;
    for (int m = g; m < 4096; m += 16) {
        float x = p[(long long)m * 1024];
        float nm = fmaxf(mx, x);
        sm = sm * __expf(mx - nm) + __expf(x - nm);
        mx = nm;
    }
    smx[g][c] = mx; ssm[g][c] = sm;
    __syncthreads();
    if (g == 0) {
        float MX = smx[0][c], SM = ssm[0][c];
#pragma unroll
        for (int k = 1; k < 16; k++) {
            float m2 = smx[k][c], s2 = ssm[k][c];
            float nm = fmaxf(MX, m2);
            SM = SM * __expf(MX - nm) + s2 * __expf(m2 - nm);
            MX = nm;
        }
        cmax[b * 1024 + col] = MX;
        csum[b * 1024 + col] = 1.f / SM;
    }
}

// normalize + split -> aT3 [B,4096,3072], pattern B
__global__ void colwrite_k(const float* __restrict__ lt,
                           const float* __restrict__ cmax, const float* __restrict__ csum,
                           __nv_bfloat16* __restrict__ out)
{
    long long i = (long long)blockIdx.x * 256 + threadIdx.x;
    int tcol = (int)(i & 1023);
    long long bm = i >> 10;
    int b = (int)(bm >> 12);
    float e = __expf(lt[i] - cmax[b * 1024 + tcol]) * csum[b * 1024 + tcol];
    __nv_bfloat16 h, l; bsplit(e, h, l);
    __nv_bfloat16* o = out + bm * 3072 + tcol;
    o[0] = h; o[1024] = h; o[2048] = l;
}

// ===========================================================================
// scalar auxiliary kernels
// ===========================================================================
__global__ void cos_k(const float* __restrict__ r1, const float* __restrict__ r2,
                      float* __restrict__ sim)
{
    int gid  = blockIdx.x * blockDim.x + threadIdx.x;
    int wid  = gid >> 5;
    int lane = gid & 31;
    if (wid >= 4 * 4096) return;
    const float* a = r1 + (long long)wid * 128;
    const float* c = r2 + (long long)wid * 128;
    float dot = 0.f, na = 0.f, nb = 0.f;
#pragma unroll
    for (int i = 0; i < 4; i++) {
        float x = a[lane + 32 * i], y = c[lane + 32 * i];
        dot += x * y; na += x * x; nb += y * y;
    }
#pragma unroll
    for (int o = 16; o; o >>= 1) {
        dot += __shfl_xor_sync(0xffffffffu, dot, o);
        na  += __shfl_xor_sync(0xffffffffu, na,  o);
        nb  += __shfl_xor_sync(0xffffffffu, nb,  o);
    }
    if (lane == 0)
        sim[wid] = dot / fmaxf(sqrtf(na) * sqrtf(nb), 1e-8f);
}

__global__ void difsim_k(const float* __restrict__ r1, const float* __restrict__ r2,
                         const float* __restrict__ sim,
                         float* __restrict__ difcat, float* __restrict__ absd)
{
    __shared__ float f1s[32][33], f2s[32][33], ss[32];
    const int b  = blockIdx.z;
    const int c0 = blockIdx.y * 32;
    const int n0 = blockIdx.x * 32;
    const int t  = threadIdx.x;
    const int tx = t & 31, ty = t >> 5;
    const long long BS = 524288;
    const float* r1b = r1 + (long long)b * BS;
    const float* r2b = r2 + (long long)b * BS;
#pragma unroll
    for (int r = 0; r < 4; r++) {
        int n = ty + 8 * r;
        f1s[n][tx] = r1b[(long long)(n0 + n) * 128 + c0 + tx];
        f2s[n][tx] = r2b[(long long)(n0 + n) * 128 + c0 + tx];
    }
    if (t < 32) ss[t] = sim[b * 4096 + n0 + t];
    __syncthreads();
#pragma unroll
    for (int r = 0; r < 4; r++) {
        int c = c0 + ty + 8 * r;
        int n = n0 + tx;
        float rv1 = r1b[(long long)c * 4096 + n];
        float rv2 = r2b[(long long)c * 4096 + n];
        float s  = ss[tx];
        float f1 = f1s[tx][ty + 8 * r];
        float f2 = f2s[tx][ty + 8 * r];
        float omns = 1.f - s;
        long long bo = (long long)b * (256LL * 4096) + (long long)c * 4096 + n;
        difcat[bo]                = f1 * omns + rv1;
        difcat[bo + 128LL * 4096] = f2 * omns + rv2;
        absd[(long long)b * BS + (long long)c * 4096 + n] =
            fabsf((f1 - f2) * s + rv1 - rv2);
    }
}

__global__ void pool_k(const float* __restrict__ absd, float* __restrict__ simp)
{
    int i = blockIdx.x * 256 + threadIdx.x;
    if (i >= 524288) return;
    int wp = i & 31, hp = (i >> 5) & 31, bc = i >> 10;
    const float* a = absd + (long long)bc * 4096 + (hp * 2) * 64 + wp * 2;
    simp[i] = 0.25f * (a[0] + a[1] + a[64] + a[65]);
}

__global__ void resize_k(const float* __restrict__ in, float* __restrict__ out)
{
    long long i = (long long)blockIdx.x * 256 + threadIdx.x;
    if (i >= 8388608LL) return;
    int x = (int)(i & 127), y = (int)((i >> 7) & 127);
    long long bc = i >> 14;
    float sx = (x + 0.5f) * 0.5f - 0.5f;
    float sy = (y + 0.5f) * 0.5f - 0.5f;
    int x0 = (int)floorf(sx), y0 = (int)floorf(sy);
    float fx = sx - x0, fy = sy - y0;
    int x1 = min(x0 + 1, 63), y1 = min(y0 + 1, 63);
    x0 = max(x0, 0); y0 = max(y0, 0);
    const float* p = in + bc * 4096;
    float v = (1.f - fy) * ((1.f - fx) * p[y0 * 64 + x0] + fx * p[y0 * 64 + x1])
            +        fy  * ((1.f - fx) * p[y1 * 64 + x0] + fx * p[y1 * 64 + x1]);
    out[i] = v;
}

// ---------------------------------------------------------------------------
extern "C" void kernel_launch(void* const* d_in, const int* in_sizes, int n_in,
                              void* d_out, int out_size)
{
    (void)in_sizes; (void)n_in; (void)out_size;
    const float* t1      = (const float*)d_in[0];
    const float* t2      = (const float*)d_in[1];
    const float* t1_w    = (const float*)d_in[2];
    const float* t1_b    = (const float*)d_in[3];
    const float* t2_w    = (const float*)d_in[4];
    const float* t2_b    = (const float*)d_in[5];
    const float* df_res_w = (const float*)d_in[6];
    const float* df_res_b = (const float*)d_in[7];
    const float* df_res_s = (const float*)d_in[8];
    const float* df_res_o = (const float*)d_in[9];
    const float* df_b0_w = (const float*)d_in[10];
    const float* df_b0_b = (const float*)d_in[11];
    const float* df_b0_s = (const float*)d_in[12];
    const float* df_b0_o = (const float*)d_in[13];
    const float* df_b1_w = (const float*)d_in[14];
    const float* df_b1_b = (const float*)d_in[15];
    const float* df_b1_s = (const float*)d_in[16];
    const float* df_b1_o = (const float*)d_in[17];
    const float* df_fu_w = (const float*)d_in[18];
    const float* df_fu_b = (const float*)d_in[19];
    const float* df_fu_s = (const float*)d_in[20];
    const float* df_fu_o = (const float*)d_in[21];
    const float* br1_w   = (const float*)d_in[22];
    const float* br1_b   = (const float*)d_in[23];
    const float* br2_w   = (const float*)d_in[24];
    const float* br2_b   = (const float*)d_in[25];
    const float* fu_w    = (const float*)d_in[26];
    const float* fu_b    = (const float*)d_in[27];
    const float* fu_s    = (const float*)d_in[28];
    const float* fu_o    = (const float*)d_in[29];
    float* out = (float*)d_out;

    float* S;
    cudaGetSymbolAddress((void**)&S, g_scratch);
    __nv_bfloat16* G;
    cudaGetSymbolAddress((void**)&G, g_bf);

    cudaFuncSetAttribute(hmma_gemm, cudaFuncAttributeMaxDynamicSharedMemorySize, 61440);
    cudaFuncSetAttribute(hconv_tap<3, 64>,  cudaFuncAttributeMaxDynamicSharedMemorySize, 46080);
    cudaFuncSetAttribute(hconv_tap<5, 64>,  cudaFuncAttributeMaxDynamicSharedMemorySize, 46080);
    cudaFuncSetAttribute(hconv_tap<3, 128>, cudaFuncAttributeMaxDynamicSharedMemorySize, 61440);
    cudaFuncSetAttribute(hconv_tap<5, 128>, cudaFuncAttributeMaxDynamicSharedMemorySize, 61440);

    float* res1    = S + F_RES1;
    float* res2    = S + F_RES2;
    float* sim     = S + F_SIM;
    float* difcat  = S + F_DIFC;
    float* absd    = S + F_ABSD;
    float* simp    = S + F_SIMP;
    float* rbuf    = S + F_R;
    float* b0b1    = S + F_B0B1;
    float* dif     = S + F_DIF;
    float* inc     = S + F_INC;
    float* logitsT = S + F_LOG;
    float* acat    = S + F_ACAT;
    float* fuse    = S + F_FUSE;
    float* cmax    = S + F_PAR;
    float* csum    = S + F_PAR + 4096;

    const long long S128 = 128LL * 4096;
    const long long S256 = 256LL * 4096;

    // ---- weight splits ----
    wsplit_k<<<128, 256>>>(t1_w,     G + W_T1W3,  256, 32768);
    wsplit_k<<<128, 256>>>(t2_w,     G + W_T2W3,  256, 32768);
    wsplit_k<<<128, 256>>>(df_res_w, G + W_RESW3, 256, 32768);
    wsplit_k<<<128, 256>>>(fu_w,     G + W_FUW3,  256, 32768);
    wsplit_k<<<64,  256>>>(df_fu_w,  G + W_DFUW3, 128, 16384);
    wsplit_tap_k<<<288,  256>>>(df_b0_w, G + W_B0T,  64,  9,  73728);
    wsplit_tap_k<<<800,  256>>>(df_b1_w, G + W_B1T,  64,  25, 204800);
    wsplit_tap_k<<<576,  256>>>(br1_w,   G + W_BR1T, 128, 9,  147456);
    wsplit_tap_k<<<1600, 256>>>(br2_w,   G + W_BR2T, 128, 25, 409600);

    // 1. res1/res2 = 1x1 (256->128) + bias
    tsplit3_k<<<dim3(128, 8, 4), 256>>>(t1, G + G_T3A, 256, 4096, 1);
    tsplit3_k<<<dim3(128, 8, 4), 256>>>(t2, G + G_T3B, 256, 4096, 1);
    hmma_gemm<<<dim3(32, 1, 4), 256, 61440>>>(G + W_T1W3, G + G_T3A, res1,
                                              t1_b, nullptr, nullptr, nullptr,
                                              768, 4096, 0, 4096LL * 768, S128, 0);
    hmma_gemm<<<dim3(32, 1, 4), 256, 61440>>>(G + W_T2W3, G + G_T3B, res2,
                                              t2_b, nullptr, nullptr, nullptr,
                                              768, 4096, 0, 4096LL * 768, S128, 0);
    // 2-4. cosine, dif mixing, avgpool; attention static operands
    cos_k<<<2048, 256>>>(res1, res2, sim);
    difsim_k<<<dim3(128, 4, 4), 256>>>(res1, res2, sim, difcat, absd);
    pool_k<<<2048, 256>>>(absd, simp);
    split3row_k<<<2048, 256>>>(simp, G + G_ATTN3);
    tsplit3_k<<<dim3(4, 32, 4), 256>>>(simp, G + G_ATTNT3, 1024, 128, 0);
    // 5. r = stdconv 1x1 (256->128)
    tsplit3_k<<<dim3(128, 8, 4), 256>>>(difcat, G + G_T3A, 256, 4096, 1);
    hmma_gemm<<<dim3(32, 1, 4), 256, 61440>>>(G + W_RESW3, G + G_T3A, rbuf,
                                              df_res_b, df_res_s, df_res_o, nullptr,
                                              768, 4096, 0, 4096LL * 768, S128, 0);
    // 6/7. inception branches: tap-GEMM over rbuf-split (shared)
    tsplit3_k<<<dim3(128, 4, 4), 256>>>(rbuf, G + G_RB3, 128, 4096, 1);
    hconv_tap<3, 64><<<dim3(32, 1, 4), 256, 46080>>>(
        G + W_B0T, G + G_RB3, b0b1, df_b0_b, df_b0_s, df_b0_o, S128);
    hconv_tap<5, 64><<<dim3(32, 1, 4), 256, 46080>>>(
        G + W_B1T, G + G_RB3, b0b1 + 64LL * 4096, df_b1_b, df_b1_s, df_b1_o, S128);
    // 8. dif = stdconv 1x1 (128->128) + r
    tsplit3_k<<<dim3(128, 4, 4), 256>>>(b0b1, G + G_BB3, 128, 4096, 1);
    hmma_gemm<<<dim3(32, 1, 4), 256, 61440>>>(G + W_DFUW3, G + G_BB3, dif,
                                              df_fu_b, df_fu_s, df_fu_o, rbuf,
                                              384, 4096, 0, 4096LL * 384, S128, S128);
    // dif-split shared by br1/br2
    tsplit3_k<<<dim3(128, 4, 4), 256>>>(dif, G + G_DIF3, 128, 4096, 1);
    // --- attention branches ---
    for (int br = 0; br < 2; br++) {
        if (br == 0)
            hconv_tap<3, 128><<<dim3(32, 1, 4), 256, 61440>>>(
                G + W_BR1T, G + G_DIF3, inc, br1_b, nullptr, nullptr, S128);
        else
            hconv_tap<5, 128><<<dim3(32, 1, 4), 256, 61440>>>(
                G + W_BR2T, G + G_DIF3, inc, br2_b, nullptr, nullptr, S128);
        tsplit3_k<<<dim3(128, 4, 4), 256>>>(inc, G + G_INCT3, 128, 4096, 0);
        // logitsT[b, pix, tok] = incT . attn
        hmma_gemm<<<dim3(8, 32, 4), 256, 61440>>>(G + G_INCT3, G + G_ATTN3, logitsT,
                                                  nullptr, nullptr, nullptr, nullptr,
                                                  384, 1024,
                                                  4096LL * 384, 1024LL * 384,
                                                  4096LL * 1024, 0);
        colstat_k<<<dim3(16, 4), 1024>>>(logitsT, cmax, csum);
        colwrite_k<<<65536, 256>>>(logitsT, cmax, csum, G + G_AT3);
        // out[b, c, pix] = attnT . aT + inc  -> acat half
        hmma_gemm<<<dim3(32, 1, 4), 256, 61440>>>(G + G_ATTNT3, G + G_AT3,
                                                  acat + (long long)br * S128,
                                                  nullptr, nullptr, nullptr, inc,
                                                  3072, 4096,
                                                  128LL * 3072, 4096LL * 3072,
                                                  S256, S128);
    }
    // 14. fused = stdconv 1x1 (256->128) + dif
    tsplit3_k<<<dim3(128, 8, 4), 256>>>(acat, G + G_T3A, 256, 4096, 1);
    hmma_gemm<<<dim3(32, 1, 4), 256, 61440>>>(G + W_FUW3, G + G_T3A, fuse,
                                              fu_b, fu_s, fu_o, dif,
                                              768, 4096, 0, 4096LL * 768, S128, S128);
    // 15. bilinear x2 upsample
    resize_k<<<32768, 256>>>(fuse, out);
}

// round 9
// speedup vs baseline: 2.1874x; 1.0105x over previous
#include <cuda_runtime.h>
#include <cuda_bf16.h>
#include <cstdint>

// ===========================================================================
// B=4, C_IN=256, C=128, H=W=64, HW=4096. out [4,128,128,128] f32.
// ALL dense ops on mma.sync bf16 HMMA, 2-term split (K'=3K):
//   A (hi,lo,hi) x B (hi,hi,lo) => Ahi.Bhi + Alo.Bhi + Ahi.Blo (err ~2^-18)
// Convs = per-tap shifted GEMMs over L2-resident split input (cp.async zfill).
// Round 9: launch order instrumented (launch #5 = hmma_gemm), wsplit merged,
// difsim emits the split operand directly.
// ===========================================================================

#define F_RES1 0LL
#define F_RES2 (F_RES1 + 2097152)
#define F_SIM  (F_RES2 + 2097152)
#define F_ABSD (F_SIM  + 16384)
#define F_SIMP (F_ABSD + 2097152)
#define F_R    (F_SIMP + 524288)
#define F_B0B1 (F_R    + 2097152)
#define F_DIF  (F_B0B1 + 2097152)
#define F_INC  (F_DIF  + 2097152)
#define F_LOG  (F_INC  + 2097152)      /* logitsT [B,4096,1024] */
#define F_ACAT (F_LOG  + 16777216)
#define F_FUSE (F_ACAT + 4194304)
#define F_PAR  (F_FUSE + 2097152)
#define F_TOTAL (F_PAR + 8192)

__device__ float g_scratch[F_TOTAL];

// bf16 scratch element offsets
#define W_T1W3   0LL         /* [128,768]        */
#define W_T2W3   98304LL
#define W_RESW3  196608LL
#define W_FUW3   294912LL
#define W_DFUW3  393216LL    /* [128,384]        */
#define W_B0T    442368LL    /* [9][64][384]     */
#define W_B1T    663552LL    /* [25][64][384]    */
#define W_BR1T   1277952LL   /* [9][128][384]    */
#define W_BR2T   1720320LL   /* [25][128][384]   */
#define G_ATTN3  2949120LL   /* [4,1024,384]     */
#define G_INCT3  4521984LL   /* [4,4096,384]     */
#define G_ATTNT3 10813440LL  /* [4,128,3072]     */
#define G_AT3    12386304LL  /* [4,4096,3072]    */
#define G_T3A    62717952LL  /* [4,4096,768]     */
#define G_T3B    75300864LL  /* [4,4096,768]     */
#define G_RB3    87883776LL  /* [4,4096,384]     */
#define G_DIF3   94175232LL  /* [4,4096,384]     */
#define G_BB3    100466688LL /* [4,4096,384]     */
#define G_TOTAL  106758144LL

__device__ __align__(256) __nv_bfloat16 g_bf[G_TOTAL];

// ------------------------------ helpers ------------------------------------
__device__ __forceinline__ uint32_t smem_u32(const void* p) {
    uint32_t a;
    asm("{ .reg .u64 t; cvta.to.shared.u64 t, %1; cvt.u32.u64 %0, t; }"
        : "=r"(a) : "l"(p));
    return a;
}
__device__ __forceinline__ void bsplit(float x, __nv_bfloat16& h, __nv_bfloat16& l) {
    h = __float2bfloat16(x);
    l = __float2bfloat16(x - __bfloat162float(h));
}
#define CP_ASYNC(dst, src) asm volatile( \
    "cp.async.cg.shared.global [%0], [%1], 16;" :: "r"(dst), "l"(src))
#define CP_ASYNC_Z(dst, src, sz) asm volatile( \
    "cp.async.cg.shared.global [%0], [%1], 16, %2;" :: "r"(dst), "l"(src), "r"(sz))
#define CP_COMMIT() asm volatile("cp.async.commit_group;" ::: "memory")
#define CP_WAIT1()  asm volatile("cp.async.wait_group 1;" ::: "memory")
#define CP_WAIT0()  asm volatile("cp.async.wait_group 0;" ::: "memory")
#define LDM_X4(r0, r1, r2, r3, a) asm volatile( \
    "ldmatrix.sync.aligned.m8n8.x4.shared.b16 {%0,%1,%2,%3}, [%4];" \
    : "=r"(r0), "=r"(r1), "=r"(r2), "=r"(r3) : "r"(a))
#define MMA16816(d, a, bfr) asm volatile( \
    "mma.sync.aligned.m16n8k16.row.col.f32.bf16.bf16.f32 " \
    "{%0,%1,%2,%3}, {%4,%5,%6,%7}, {%8,%9}, {%0,%1,%2,%3};" \
    : "+f"((d)[0]), "+f"((d)[1]), "+f"((d)[2]), "+f"((d)[3]) \
    : "r"((a)[0]), "r"((a)[1]), "r"((a)[2]), "r"((a)[3]), \
      "r"((bfr)[0]), "r"((bfr)[1]))

// ===========================================================================
// hmma_gemm: 128x128 tile, 8 warps (32m x 64n), chunk k=32, 3-stage cp.async.
// ===========================================================================
__global__ void __launch_bounds__(256) hmma_gemm(
    const __nv_bfloat16* __restrict__ A3, const __nv_bfloat16* __restrict__ B3,
    float* __restrict__ C,
    const float* __restrict__ bias, const float* __restrict__ scale,
    const float* __restrict__ off, const float* __restrict__ resid,
    int Kp, int Ncols,
    long long Abs, long long Bbs, long long Cbs, long long Rbs)
{
    extern __shared__ __align__(16) char smbuf[];
    const uint32_t sA = smem_u32(smbuf);          // 3 stages x 10240
    const uint32_t sB = sA + 30720;               // 3 stages x 10240
    const int t = threadIdx.x, lane = t & 31, wid = t >> 5;
    const int wm = wid & 3, wn = wid >> 2;
    const int b  = blockIdx.z;
    const int m0 = blockIdx.y * 128;
    const int n0 = blockIdx.x * 128;
    const __nv_bfloat16* Ab = A3 + (long long)b * Abs + (long long)m0 * Kp;
    const __nv_bfloat16* Bb = B3 + (long long)b * Bbs + (long long)n0 * Kp;

    float acc[2][8][4];
#pragma unroll
    for (int i = 0; i < 2; i++)
#pragma unroll
        for (int j = 0; j < 8; j++)
#pragma unroll
            for (int r = 0; r < 4; r++) acc[i][j][r] = 0.f;

    auto ldch = [&](int c) {
        const uint32_t ao = sA + (c % 3) * 10240;
        const uint32_t bo = sB + (c % 3) * 10240;
#pragma unroll
        for (int r = 0; r < 2; r++) {
            int f = t + 256 * r, row = f >> 2, kq = f & 3;
            CP_ASYNC(ao + (uint32_t)(row * 80 + kq * 16),
                     Ab + (long long)row * Kp + c * 32 + kq * 8);
            CP_ASYNC(bo + (uint32_t)(row * 80 + kq * 16),
                     Bb + (long long)row * Kp + c * 32 + kq * 8);
        }
        CP_COMMIT();
    };

    const int nch = Kp >> 5;
    ldch(0);
    if (nch > 1) ldch(1);
    for (int c = 0; c < nch; c++) {
        if (c + 1 < nch) CP_WAIT1(); else CP_WAIT0();
        __syncthreads();
        if (c + 2 < nch) ldch(c + 2);
        const uint32_t ao = sA + (c % 3) * 10240;
        const uint32_t bo = sB + (c % 3) * 10240;
#pragma unroll
        for (int ks = 0; ks < 2; ks++) {
            const int kb = ks * 16;
            uint32_t af[2][4];
#pragma unroll
            for (int i = 0; i < 2; i++) {
                int row = wm * 32 + i * 16 + (lane & 7) + ((lane >> 3) & 1) * 8;
                int col = kb + ((lane >> 4) & 1) * 8;
                LDM_X4(af[i][0], af[i][1], af[i][2], af[i][3],
                       ao + (uint32_t)(row * 80 + col * 2));
            }
            uint32_t bfr[8][2];
#pragma unroll
            for (int jp = 0; jp < 4; jp++) {
                int n = wn * 64 + jp * 16 + (lane & 7) + ((lane >> 4) & 1) * 8;
                int k = kb + ((lane >> 3) & 1) * 8;
                LDM_X4(bfr[2 * jp][0], bfr[2 * jp][1],
                       bfr[2 * jp + 1][0], bfr[2 * jp + 1][1],
                       bo + (uint32_t)(n * 80 + k * 2));
            }
#pragma unroll
            for (int i = 0; i < 2; i++)
#pragma unroll
                for (int j = 0; j < 8; j++)
                    MMA16816(acc[i][j], af[i], bfr[j]);
        }
        __syncthreads();
    }

    float* Cb = C + (long long)b * Cbs;
    const float* Rb = resid ? resid + (long long)b * Rbs : nullptr;
#pragma unroll
    for (int i = 0; i < 2; i++)
#pragma unroll
        for (int h = 0; h < 2; h++) {
            int m = m0 + wm * 32 + i * 16 + (lane >> 2) + h * 8;
            float bi = bias  ? bias[m]  : 0.f;
            float sc = scale ? scale[m] : 1.f;
            float ofv = off  ? off[m]   : 0.f;
            float* crow = Cb + (long long)m * Ncols;
            const float* rrow = Rb ? Rb + (long long)m * Ncols : nullptr;
#pragma unroll
            for (int j = 0; j < 8; j++) {
                int col = n0 + wn * 64 + j * 8 + (lane & 3) * 2;
                float2 v = make_float2(acc[i][j][h * 2 + 0] + bi,
                                       acc[i][j][h * 2 + 1] + bi);
                if (scale) {
                    v.x = fmaxf(v.x, 0.f) * sc + ofv;
                    v.y = fmaxf(v.y, 0.f) * sc + ofv;
                }
                if (rrow) {
                    float2 rv = *(const float2*)(rrow + col);
                    v.x += rv.x; v.y += rv.y;
                }
                *(float2*)(crow + col) = v;
            }
        }
}

// ===========================================================================
// hconv_tap: conv KSxKS (pad KS/2) as sum of per-tap shifted GEMMs.
// ===========================================================================
template <int KS, int MT>
__global__ void __launch_bounds__(256) hconv_tap(
    const __nv_bfloat16* __restrict__ W3t, const __nv_bfloat16* __restrict__ Bsplit,
    float* __restrict__ out,
    const float* __restrict__ bias, const float* __restrict__ scale,
    const float* __restrict__ off, long long out_bstride)
{
    constexpr int P    = KS / 2;
    constexpr int TAPS = KS * KS;
    constexpr int NC   = TAPS * 12;
    constexpr int WM_N = MT / 32;
    constexpr int WN_N = 8 / WM_N;
    constexpr int NJ   = 128 / (WN_N * 8);
    constexpr int ASTG = MT * 80;
    extern __shared__ __align__(16) char smbuf[];
    const uint32_t sA = smem_u32(smbuf);
    const uint32_t sB = sA + 3 * ASTG;
    const int t = threadIdx.x, lane = t & 31, wid = t >> 5;
    const int wm = wid % WM_N, wn = wid / WM_N;
    const int b  = blockIdx.z;
    const int n0 = blockIdx.x * 128;
    const __nv_bfloat16* Bb = Bsplit + (long long)b * (4096LL * 384);

    float acc[2][NJ][4];
#pragma unroll
    for (int i = 0; i < 2; i++)
#pragma unroll
        for (int j = 0; j < NJ; j++)
#pragma unroll
            for (int r = 0; r < 4; r++) acc[i][j][r] = 0.f;

    auto ldch = [&](int gc) {
        const int tap = gc / 12;
        const int c   = gc - tap * 12;
        const int dy  = tap / KS - P, dx = tap - (tap / KS) * KS - P;
        const int shift = dy * 64 + dx;
        const uint32_t ao = sA + (gc % 3) * ASTG;
        const uint32_t bo = sB + (gc % 3) * 10240;
#pragma unroll
        for (int r = 0; r < MT / 64; r++) {
            int f = t + 256 * r, row = f >> 2, kq = f & 3;
            CP_ASYNC(ao + (uint32_t)(row * 80 + kq * 16),
                     W3t + (long long)tap * (MT * 384) + (long long)row * 384
                         + c * 32 + kq * 8);
        }
#pragma unroll
        for (int r = 0; r < 2; r++) {
            int f = t + 256 * r, row = f >> 2, kq = f & 3;
            int gpix = n0 + row;
            int y = gpix >> 6, x = gpix & 63;
            bool ok = ((unsigned)(y + dy) < 64u) && ((unsigned)(x + dx) < 64u);
            int spix = ok ? (gpix + shift) : 0;
            uint32_t sz = ok ? 16u : 0u;
            CP_ASYNC_Z(bo + (uint32_t)(row * 80 + kq * 16),
                       Bb + (long long)spix * 384 + c * 32 + kq * 8, sz);
        }
        CP_COMMIT();
    };

    ldch(0);
    ldch(1);
    for (int gc = 0; gc < NC; gc++) {
        if (gc + 1 < NC) CP_WAIT1(); else CP_WAIT0();
        __syncthreads();
        if (gc + 2 < NC) ldch(gc + 2);
        const uint32_t ao = sA + (gc % 3) * ASTG;
        const uint32_t bo = sB + (gc % 3) * 10240;
#pragma unroll
        for (int ks = 0; ks < 2; ks++) {
            const int kb = ks * 16;
            uint32_t af[2][4];
#pragma unroll
            for (int i = 0; i < 2; i++) {
                int row = wm * 32 + i * 16 + (lane & 7) + ((lane >> 3) & 1) * 8;
                int col = kb + ((lane >> 4) & 1) * 8;
                LDM_X4(af[i][0], af[i][1], af[i][2], af[i][3],
                       ao + (uint32_t)(row * 80 + col * 2));
            }
            uint32_t bfr[NJ][2];
#pragma unroll
            for (int jp = 0; jp < NJ / 2; jp++) {
                int n = wn * (NJ * 8) + jp * 16 + (lane & 7) + ((lane >> 4) & 1) * 8;
                int k = kb + ((lane >> 3) & 1) * 8;
                LDM_X4(bfr[2 * jp][0], bfr[2 * jp][1],
                       bfr[2 * jp + 1][0], bfr[2 * jp + 1][1],
                       bo + (uint32_t)(n * 80 + k * 2));
            }
#pragma unroll
            for (int i = 0; i < 2; i++)
#pragma unroll
                for (int j = 0; j < NJ; j++)
                    MMA16816(acc[i][j], af[i], bfr[j]);
        }
        __syncthreads();
    }

    float* Ob = out + (long long)b * out_bstride;
#pragma unroll
    for (int i = 0; i < 2; i++)
#pragma unroll
        for (int h = 0; h < 2; h++) {
            int m = wm * 32 + i * 16 + (lane >> 2) + h * 8;
            float bi = bias[m];
            float sc = scale ? scale[m] : 1.f;
            float ofv = off ? off[m] : 0.f;
            float* crow = Ob + (long long)m * 4096;
#pragma unroll
            for (int j = 0; j < NJ; j++) {
                int col = n0 + wn * (NJ * 8) + j * 8 + (lane & 3) * 2;
                float2 v = make_float2(acc[i][j][h * 2 + 0] + bi,
                                       acc[i][j][h * 2 + 1] + bi);
                if (scale) {
                    v.x = fmaxf(v.x, 0.f) * sc + ofv;
                    v.y = fmaxf(v.y, 0.f) * sc + ofv;
                }
                *(float2*)(crow + col) = v;
            }
        }
}

// ===========================================================================
// prep kernels
// ===========================================================================
// all five 1x1 weight splits in one launch. grid (128, 5).
__global__ void wsplit5_k(const float* s0, const float* s1, const float* s2,
                          const float* s3, const float* s4,
                          __nv_bfloat16* d0, __nv_bfloat16* d1, __nv_bfloat16* d2,
                          __nv_bfloat16* d3, __nv_bfloat16* d4)
{
    const int seg = blockIdx.y;
    const float* src; __nv_bfloat16* dst; int K, total;
    switch (seg) {
        case 0: src = s0; dst = d0; K = 256; total = 32768; break;
        case 1: src = s1; dst = d1; K = 256; total = 32768; break;
        case 2: src = s2; dst = d2; K = 256; total = 32768; break;
        case 3: src = s3; dst = d3; K = 256; total = 32768; break;
        default: src = s4; dst = d4; K = 128; total = 16384; break;
    }
    int i = blockIdx.x * 256 + threadIdx.x;
    if (i >= total) return;
    int m = i / K, k = i - m * K;
    __nv_bfloat16 h, l; bsplit(src[i], h, l);
    __nv_bfloat16* o = dst + (long long)m * 3 * K + k;
    o[0] = h; o[K] = l; o[2 * K] = h;
}

// conv weight split: src OIHW f32 [Cout,128,KS2] -> dst [tap][Cout][384] (hi,lo,hi)
__global__ void wsplit_tap_k(const float* __restrict__ src, __nv_bfloat16* __restrict__ dst,
                             int Cout, int KS2, int total)
{
    int i = blockIdx.x * 256 + threadIdx.x;
    if (i >= total) return;
    int co = i / (128 * KS2);
    int rem = i - co * 128 * KS2;
    int ci = rem / KS2;
    int tap = rem - ci * KS2;
    __nv_bfloat16 h, l; bsplit(src[i], h, l);
    __nv_bfloat16* o = dst + (long long)tap * Cout * 384 + (long long)co * 384 + ci;
    o[0] = h; o[128] = l; o[256] = h;
}

// transpose+split: in [B,R,Ncol] f32 -> out [B,Ncol,3R] bf16.
__global__ void tsplit3_k(const float* __restrict__ in, __nv_bfloat16* __restrict__ out,
                          int R, int Ncol, int patB)
{
    __shared__ float tile[32][33];
    const int b = blockIdx.z, r0 = blockIdx.y * 32, n0 = blockIdx.x * 32;
    const int tx = threadIdx.x & 31, ty = threadIdx.x >> 5;
    const float* ib = in + (long long)b * R * Ncol;
#pragma unroll
    for (int p = 0; p < 4; p++)
        tile[ty + 8 * p][tx] = ib[(long long)(r0 + ty + 8 * p) * Ncol + n0 + tx];
    __syncthreads();
    __nv_bfloat16* ob = out + (long long)b * Ncol * 3 * R;
#pragma unroll
    for (int p = 0; p < 4; p++) {
        int n = n0 + ty + 8 * p, r = r0 + tx;
        float x = tile[tx][ty + 8 * p];
        __nv_bfloat16 h, l; bsplit(x, h, l);
        __nv_bfloat16* o = ob + (long long)n * 3 * R;
        if (patB) { o[r] = h; o[R + r] = h; o[2 * R + r] = l; }
        else      { o[r] = h; o[R + r] = l; o[2 * R + r] = h; }
    }
}

// attn3: simp [B*1024,128] f32 -> [B,1024,384] bf16, pattern B
__global__ void split3row_k(const float* __restrict__ in, __nv_bfloat16* __restrict__ out)
{
    int i = blockIdx.x * 256 + threadIdx.x;
    float x = in[i];
    __nv_bfloat16 h, l; bsplit(x, h, l);
    long long row = i >> 7; int c = i & 127;
    __nv_bfloat16* o = out + row * 384 + c;
    o[0] = h; o[128] = h; o[256] = l;
}

// fused difsim: writes absd f32 AND the difcat split operand [B,4096,768] (hi,hi,lo)
__global__ void difsim_split_k(const float* __restrict__ r1, const float* __restrict__ r2,
                               const float* __restrict__ sim,
                               __nv_bfloat16* __restrict__ dsplit,
                               float* __restrict__ absd)
{
    __shared__ float f1s[32][33], f2s[32][33], d1s[32][33], d2s[32][33], ss[32];
    const int b  = blockIdx.z;
    const int c0 = blockIdx.y * 32;
    const int n0 = blockIdx.x * 32;
    const int t  = threadIdx.x;
    const int tx = t & 31, ty = t >> 5;
    const long long BS = 524288;
    const float* r1b = r1 + (long long)b * BS;
    const float* r2b = r2 + (long long)b * BS;
#pragma unroll
    for (int r = 0; r < 4; r++) {
        int n = ty + 8 * r;
        f1s[n][tx] = r1b[(long long)(n0 + n) * 128 + c0 + tx];
        f2s[n][tx] = r2b[(long long)(n0 + n) * 128 + c0 + tx];
    }
    if (t < 32) ss[t] = sim[b * 4096 + n0 + t];
    __syncthreads();
#pragma unroll
    for (int r = 0; r < 4; r++) {
        int cl = ty + 8 * r;            // local channel
        int c = c0 + cl;
        int n = n0 + tx;
        float rv1 = r1b[(long long)c * 4096 + n];
        float rv2 = r2b[(long long)c * 4096 + n];
        float s  = ss[tx];
        float f1 = f1s[tx][cl];
        float f2 = f2s[tx][cl];
        float omns = 1.f - s;
        float d1 = f1 * omns + rv1;
        float d2 = f2 * omns + rv2;
        d1s[cl][tx] = d1;
        d2s[cl][tx] = d2;
        absd[(long long)b * BS + (long long)c * 4096 + n] =
            fabsf((f1 - f2) * s + rv1 - rv2);
    }
    __syncthreads();
    // write split rows: for pixel n, K=256 channels, layout [hi(256),hi(256),lo(256)]
#pragma unroll
    for (int p = 0; p < 4; p++) {
        int nl = ty + 8 * p;
        float d1 = d1s[tx][nl];
        float d2 = d2s[tx][nl];
        __nv_bfloat16 h1, l1, h2, l2;
        bsplit(d1, h1, l1);
        bsplit(d2, h2, l2);
        __nv_bfloat16* orow = dsplit + (long long)b * (4096LL * 768)
                            + (long long)(n0 + nl) * 768;
        orow[c0 + tx]       = h1;
        orow[128 + c0 + tx] = h2;
        orow[256 + c0 + tx] = h1;
        orow[384 + c0 + tx] = h2;
        orow[512 + c0 + tx] = l1;
        orow[640 + c0 + tx] = l2;
    }
}

// column softmax stats over logitsT [B,4096,1024]
__global__ void colstat_k(const float* __restrict__ lt,
                          float* __restrict__ cmax, float* __restrict__ csum)
{
    __shared__ float smx[16][65], ssm[16][65];
    const int b = blockIdx.y;
    const int c = threadIdx.x & 63, g = threadIdx.x >> 6;
    const int col = blockIdx.x * 64 + c;
    const float* p = lt + (long long)b * 4194304 + col;
    float mx = -1e30f, sm = 0.f;
    for (int m = g; m < 4096; m += 16) {
        float x = p[(long long)m * 1024];
        float nm = fmaxf(mx, x);
        sm = sm * __expf(mx - nm) + __expf(x - nm);
        mx = nm;
    }
    smx[g][c] = mx; ssm[g][c] = sm;
    __syncthreads();
    if (g == 0) {
        float MX = smx[0][c], SM = ssm[0][c];
#pragma unroll
        for (int k = 1; k < 16; k++) {
            float m2 = smx[k][c], s2 = ssm[k][c];
            float nm = fmaxf(MX, m2);
            SM = SM * __expf(MX - nm) + s2 * __expf(m2 - nm);
            MX = nm;
        }
        cmax[b * 1024 + col] = MX;
        csum[b * 1024 + col] = 1.f / SM;
    }
}

// normalize + split -> aT3 [B,4096,3072], pattern B
__global__ void colwrite_k(const float* __restrict__ lt,
                           const float* __restrict__ cmax, const float* __restrict__ csum,
                           __nv_bfloat16* __restrict__ out)
{
    long long i = (long long)blockIdx.x * 256 + threadIdx.x;
    int tcol = (int)(i & 1023);
    long long bm = i >> 10;
    int b = (int)(bm >> 12);
    float e = __expf(lt[i] - cmax[b * 1024 + tcol]) * csum[b * 1024 + tcol];
    __nv_bfloat16 h, l; bsplit(e, h, l);
    __nv_bfloat16* o = out + bm * 3072 + tcol;
    o[0] = h; o[1024] = h; o[2048] = l;
}

// ===========================================================================
// scalar auxiliary kernels
// ===========================================================================
__global__ void cos_k(const float* __restrict__ r1, const float* __restrict__ r2,
                      float* __restrict__ sim)
{
    int gid  = blockIdx.x * blockDim.x + threadIdx.x;
    int wid  = gid >> 5;
    int lane = gid & 31;
    if (wid >= 4 * 4096) return;
    const float* a = r1 + (long long)wid * 128;
    const float* c = r2 + (long long)wid * 128;
    float dot = 0.f, na = 0.f, nb = 0.f;
#pragma unroll
    for (int i = 0; i < 4; i++) {
        float x = a[lane + 32 * i], y = c[lane + 32 * i];
        dot += x * y; na += x * x; nb += y * y;
    }
#pragma unroll
    for (int o = 16; o; o >>= 1) {
        dot += __shfl_xor_sync(0xffffffffu, dot, o);
        na  += __shfl_xor_sync(0xffffffffu, na,  o);
        nb  += __shfl_xor_sync(0xffffffffu, nb,  o);
    }
    if (lane == 0)
        sim[wid] = dot / fmaxf(sqrtf(na) * sqrtf(nb), 1e-8f);
}

__global__ void pool_k(const float* __restrict__ absd, float* __restrict__ simp)
{
    int i = blockIdx.x * 256 + threadIdx.x;
    if (i >= 524288) return;
    int wp = i & 31, hp = (i >> 5) & 31, bc = i >> 10;
    const float* a = absd + (long long)bc * 4096 + (hp * 2) * 64 + wp * 2;
    simp[i] = 0.25f * (a[0] + a[1] + a[64] + a[65]);
}

__global__ void resize_k(const float* __restrict__ in, float* __restrict__ out)
{
    long long i = (long long)blockIdx.x * 256 + threadIdx.x;
    if (i >= 8388608LL) return;
    int x = (int)(i & 127), y = (int)((i >> 7) & 127);
    long long bc = i >> 14;
    float sx = (x + 0.5f) * 0.5f - 0.5f;
    float sy = (y + 0.5f) * 0.5f - 0.5f;
    int x0 = (int)floorf(sx), y0 = (int)floorf(sy);
    float fx = sx - x0, fy = sy - y0;
    int x1 = min(x0 + 1, 63), y1 = min(y0 + 1, 63);
    x0 = max(x0, 0); y0 = max(y0, 0);
    const float* p = in + bc * 4096;
    float v = (1.f - fy) * ((1.f - fx) * p[y0 * 64 + x0] + fx * p[y0 * 64 + x1])
            +        fy  * ((1.f - fx) * p[y1 * 64 + x0] + fx * p[y1 * 64 + x1]);
    out[i] = v;
}

// ---------------------------------------------------------------------------
extern "C" void kernel_launch(void* const* d_in, const int* in_sizes, int n_in,
                              void* d_out, int out_size)
{
    (void)in_sizes; (void)n_in; (void)out_size;
    const float* t1      = (const float*)d_in[0];
    const float* t2      = (const float*)d_in[1];
    const float* t1_w    = (const float*)d_in[2];
    const float* t1_b    = (const float*)d_in[3];
    const float* t2_w    = (const float*)d_in[4];
    const float* t2_b    = (const float*)d_in[5];
    const float* df_res_w = (const float*)d_in[6];
    const float* df_res_b = (const float*)d_in[7];
    const float* df_res_s = (const float*)d_in[8];
    const float* df_res_o = (const float*)d_in[9];
    const float* df_b0_w = (const float*)d_in[10];
    const float* df_b0_b = (const float*)d_in[11];
    const float* df_b0_s = (const float*)d_in[12];
    const float* df_b0_o = (const float*)d_in[13];
    const float* df_b1_w = (const float*)d_in[14];
    const float* df_b1_b = (const float*)d_in[15];
    const float* df_b1_s = (const float*)d_in[16];
    const float* df_b1_o = (const float*)d_in[17];
    const float* df_fu_w = (const float*)d_in[18];
    const float* df_fu_b = (const float*)d_in[19];
    const float* df_fu_s = (const float*)d_in[20];
    const float* df_fu_o = (const float*)d_in[21];
    const float* br1_w   = (const float*)d_in[22];
    const float* br1_b   = (const float*)d_in[23];
    const float* br2_w   = (const float*)d_in[24];
    const float* br2_b   = (const float*)d_in[25];
    const float* fu_w    = (const float*)d_in[26];
    const float* fu_b    = (const float*)d_in[27];
    const float* fu_s    = (const float*)d_in[28];
    const float* fu_o    = (const float*)d_in[29];
    float* out = (float*)d_out;

    float* S;
    cudaGetSymbolAddress((void**)&S, g_scratch);
    __nv_bfloat16* G;
    cudaGetSymbolAddress((void**)&G, g_bf);

    cudaFuncSetAttribute(hmma_gemm, cudaFuncAttributeMaxDynamicSharedMemorySize, 61440);
    cudaFuncSetAttribute(hconv_tap<3, 64>,  cudaFuncAttributeMaxDynamicSharedMemorySize, 46080);
    cudaFuncSetAttribute(hconv_tap<5, 64>,  cudaFuncAttributeMaxDynamicSharedMemorySize, 46080);
    cudaFuncSetAttribute(hconv_tap<3, 128>, cudaFuncAttributeMaxDynamicSharedMemorySize, 61440);
    cudaFuncSetAttribute(hconv_tap<5, 128>, cudaFuncAttributeMaxDynamicSharedMemorySize, 61440);

    float* res1    = S + F_RES1;
    float* res2    = S + F_RES2;
    float* sim     = S + F_SIM;
    float* absd    = S + F_ABSD;
    float* simp    = S + F_SIMP;
    float* rbuf    = S + F_R;
    float* b0b1    = S + F_B0B1;
    float* dif     = S + F_DIF;
    float* inc     = S + F_INC;
    float* logitsT = S + F_LOG;
    float* acat    = S + F_ACAT;
    float* fuse    = S + F_FUSE;
    float* cmax    = S + F_PAR;
    float* csum    = S + F_PAR + 4096;

    const long long S128 = 128LL * 4096;
    const long long S256 = 256LL * 4096;

    // launches 0..5 arranged so ncu (-s 5) profiles hmma_gemm (res2)
    // 0: all five 1x1 weight splits
    wsplit5_k<<<dim3(128, 5), 256>>>(t1_w, t2_w, df_res_w, fu_w, df_fu_w,
                                     G + W_T1W3, G + W_T2W3, G + W_RESW3,
                                     G + W_FUW3, G + W_DFUW3);
    // 1: tap split b0 (others later)
    wsplit_tap_k<<<288, 256>>>(df_b0_w, G + W_B0T, 64, 9, 73728);
    // 2,3: input splits
    tsplit3_k<<<dim3(128, 8, 4), 256>>>(t1, G + G_T3A, 256, 4096, 1);
    tsplit3_k<<<dim3(128, 8, 4), 256>>>(t2, G + G_T3B, 256, 4096, 1);
    // 4,5: res GEMMs (launch #5 = engine profile target)
    hmma_gemm<<<dim3(32, 1, 4), 256, 61440>>>(G + W_T1W3, G + G_T3A, res1,
                                              t1_b, nullptr, nullptr, nullptr,
                                              768, 4096, 0, 4096LL * 768, S128, 0);
    hmma_gemm<<<dim3(32, 1, 4), 256, 61440>>>(G + W_T2W3, G + G_T3B, res2,
                                              t2_b, nullptr, nullptr, nullptr,
                                              768, 4096, 0, 4096LL * 768, S128, 0);
    // cosine, fused dif-split (writes G_T3A), avgpool, attn operands
    cos_k<<<2048, 256>>>(res1, res2, sim);
    difsim_split_k<<<dim3(128, 4, 4), 256>>>(res1, res2, sim, G + G_T3A, absd);
    pool_k<<<2048, 256>>>(absd, simp);
    split3row_k<<<2048, 256>>>(simp, G + G_ATTN3);
    tsplit3_k<<<dim3(4, 32, 4), 256>>>(simp, G + G_ATTNT3, 1024, 128, 0);
    // remaining tap weight splits
    wsplit_tap_k<<<800,  256>>>(df_b1_w, G + W_B1T,  64,  25, 204800);
    wsplit_tap_k<<<576,  256>>>(br1_w,   G + W_BR1T, 128, 9,  147456);
    wsplit_tap_k<<<1600, 256>>>(br2_w,   G + W_BR2T, 128, 25, 409600);
    // 5. r = stdconv 1x1 (256->128) over fused difcat split
    hmma_gemm<<<dim3(32, 1, 4), 256, 61440>>>(G + W_RESW3, G + G_T3A, rbuf,
                                              df_res_b, df_res_s, df_res_o, nullptr,
                                              768, 4096, 0, 4096LL * 768, S128, 0);
    // 6/7. inception branches over shared rbuf-split
    tsplit3_k<<<dim3(128, 4, 4), 256>>>(rbuf, G + G_RB3, 128, 4096, 1);
    hconv_tap<3, 64><<<dim3(32, 1, 4), 256, 46080>>>(
        G + W_B0T, G + G_RB3, b0b1, df_b0_b, df_b0_s, df_b0_o, S128);
    hconv_tap<5, 64><<<dim3(32, 1, 4), 256, 46080>>>(
        G + W_B1T, G + G_RB3, b0b1 + 64LL * 4096, df_b1_b, df_b1_s, df_b1_o, S128);
    // 8. dif = stdconv 1x1 (128->128) + r
    tsplit3_k<<<dim3(128, 4, 4), 256>>>(b0b1, G + G_BB3, 128, 4096, 1);
    hmma_gemm<<<dim3(32, 1, 4), 256, 61440>>>(G + W_DFUW3, G + G_BB3, dif,
                                              df_fu_b, df_fu_s, df_fu_o, rbuf,
                                              384, 4096, 0, 4096LL * 384, S128, S128);
    tsplit3_k<<<dim3(128, 4, 4), 256>>>(dif, G + G_DIF3, 128, 4096, 1);
    // --- attention branches ---
    for (int br = 0; br < 2; br++) {
        if (br == 0)
            hconv_tap<3, 128><<<dim3(32, 1, 4), 256, 61440>>>(
                G + W_BR1T, G + G_DIF3, inc, br1_b, nullptr, nullptr, S128);
        else
            hconv_tap<5, 128><<<dim3(32, 1, 4), 256, 61440>>>(
                G + W_BR2T, G + G_DIF3, inc, br2_b, nullptr, nullptr, S128);
        tsplit3_k<<<dim3(128, 4, 4), 256>>>(inc, G + G_INCT3, 128, 4096, 0);
        hmma_gemm<<<dim3(8, 32, 4), 256, 61440>>>(G + G_INCT3, G + G_ATTN3, logitsT,
                                                  nullptr, nullptr, nullptr, nullptr,
                                                  384, 1024,
                                                  4096LL * 384, 1024LL * 384,
                                                  4096LL * 1024, 0);
        colstat_k<<<dim3(16, 4), 1024>>>(logitsT, cmax, csum);
        colwrite_k<<<65536, 256>>>(logitsT, cmax, csum, G + G_AT3);
        hmma_gemm<<<dim3(32, 1, 4), 256, 61440>>>(G + G_ATTNT3, G + G_AT3,
                                                  acat + (long long)br * S128,
                                                  nullptr, nullptr, nullptr, inc,
                                                  3072, 4096,
                                                  128LL * 3072, 4096LL * 3072,
                                                  S256, S128);
    }
    // 14. fused = stdconv 1x1 (256->128) + dif
    tsplit3_k<<<dim3(128, 8, 4), 256>>>(acat, G + G_T3A, 256, 4096, 1);
    hmma_gemm<<<dim3(32, 1, 4), 256, 61440>>>(G + W_FUW3, G + G_T3A, fuse,
                                              fu_b, fu_s, fu_o, dif,
                                              768, 4096, 0, 4096LL * 768, S128, S128);
    // 15. bilinear x2 upsample
    resize_k<<<32768, 256>>>(fuse, out);
}

// round 10
// speedup vs baseline: 2.2945x; 1.0489x over previous
#include <cuda_runtime.h>
#include <cuda_bf16.h>
#include <cstdint>

// ===========================================================================
// B=4, C_IN=256, C=128, H=W=64, HW=4096. out [4,128,128,128] f32.
// ALL dense ops on mma.sync bf16 HMMA, 2-term split.
// Split operands stored 2-segment [hi|lo]; GEMM walks a 3-segment schedule:
//   (Ahi,Bhi) + (Alo,Bhi) + (Ahi,Blo)   (err ~2^-18)
// Convs = per-tap shifted GEMMs over L2-resident split input (cp.async zfill).
// Softmax stats+normalize fused (one DRAM pass saved).
// ===========================================================================

#define F_RES1 0LL
#define F_RES2 (F_RES1 + 2097152)
#define F_SIM  (F_RES2 + 2097152)
#define F_ABSD (F_SIM  + 16384)
#define F_SIMP (F_ABSD + 2097152)
#define F_R    (F_SIMP + 524288)
#define F_B0B1 (F_R    + 2097152)
#define F_DIF  (F_B0B1 + 2097152)
#define F_INC  (F_DIF  + 2097152)
#define F_LOG  (F_INC  + 2097152)      /* logitsT [B,4096,1024] */
#define F_ACAT (F_LOG  + 16777216)
#define F_FUSE (F_ACAT + 4194304)
#define F_TOTAL (F_FUSE + 2097152)

__device__ float g_scratch[F_TOTAL];

// bf16 scratch element offsets (2-segment layouts)
#define W_T1W2   0LL         /* [128,512]       */
#define W_T2W2   65536LL
#define W_RESW2  131072LL
#define W_FUW2   196608LL
#define W_DFUW2  262144LL    /* [128,256]       */
#define W_B0T    294912LL    /* [9][64][256]    */
#define W_B1T    442368LL    /* [25][64][256]   */
#define W_BR1T   851968LL    /* [9][128][256]   */
#define W_BR2T   1146880LL   /* [25][128][256]  */
#define G_ATTN2  1966080LL   /* [4,1024,256]    */
#define G_INCT2  3014656LL   /* [4,4096,256]    */
#define G_ATTNT2 7208960LL   /* [4,128,2048]    */
#define G_AT2    8257536LL   /* [4,4096,2048]   */
#define G_T3A    41811968LL  /* [4,4096,512]    */
#define G_T3B    50200576LL  /* [4,4096,512]    */
#define G_RB2    58589184LL  /* [4,4096,256]    */
#define G_DIF2   62783488LL  /* [4,4096,256]    */
#define G_BB2    66977792LL  /* [4,4096,256]    */
#define G_TOTAL  71172096LL

__device__ __align__(256) __nv_bfloat16 g_bf[G_TOTAL];

// ------------------------------ helpers ------------------------------------
__device__ __forceinline__ uint32_t smem_u32(const void* p) {
    uint32_t a;
    asm("{ .reg .u64 t; cvta.to.shared.u64 t, %1; cvt.u32.u64 %0, t; }"
        : "=r"(a) : "l"(p));
    return a;
}
__device__ __forceinline__ void bsplit(float x, __nv_bfloat16& h, __nv_bfloat16& l) {
    h = __float2bfloat16(x);
    l = __float2bfloat16(x - __bfloat162float(h));
}
#define CP_ASYNC(dst, src) asm volatile( \
    "cp.async.cg.shared.global [%0], [%1], 16;" :: "r"(dst), "l"(src))
#define CP_ASYNC_Z(dst, src, sz) asm volatile( \
    "cp.async.cg.shared.global [%0], [%1], 16, %2;" :: "r"(dst), "l"(src), "r"(sz))
#define CP_COMMIT() asm volatile("cp.async.commit_group;" ::: "memory")
#define CP_WAIT1()  asm volatile("cp.async.wait_group 1;" ::: "memory")
#define CP_WAIT0()  asm volatile("cp.async.wait_group 0;" ::: "memory")
#define LDM_X4(r0, r1, r2, r3, a) asm volatile( \
    "ldmatrix.sync.aligned.m8n8.x4.shared.b16 {%0,%1,%2,%3}, [%4];" \
    : "=r"(r0), "=r"(r1), "=r"(r2), "=r"(r3) : "r"(a))
#define MMA16816(d, a, bfr) asm volatile( \
    "mma.sync.aligned.m16n8k16.row.col.f32.bf16.bf16.f32 " \
    "{%0,%1,%2,%3}, {%4,%5,%6,%7}, {%8,%9}, {%0,%1,%2,%3};" \
    : "+f"((d)[0]), "+f"((d)[1]), "+f"((d)[2]), "+f"((d)[3]) \
    : "r"((a)[0]), "r"((a)[1]), "r"((a)[2]), "r"((a)[3]), \
      "r"((bfr)[0]), "r"((bfr)[1]))

// ===========================================================================
// hmma_gemm: 128x128 tile, 8 warps (32m x 64n), chunk k=32, 3-stage cp.async.
// A2 [Mtot, 2*Kcore], B2 [Ntot, 2*Kcore] bf16 (hi|lo).
// 3-segment schedule: (0,0), (Kcore,0), (0,Kcore). Kcore % 32 == 0.
// ===========================================================================
__global__ void __launch_bounds__(256) hmma_gemm(
    const __nv_bfloat16* __restrict__ A2, const __nv_bfloat16* __restrict__ B2,
    float* __restrict__ C,
    const float* __restrict__ bias, const float* __restrict__ scale,
    const float* __restrict__ off, const float* __restrict__ resid,
    int Kcore, int Ncols,
    long long Abs, long long Bbs, long long Cbs, long long Rbs)
{
    extern __shared__ __align__(16) char smbuf[];
    const uint32_t sA = smem_u32(smbuf);          // 3 stages x 10240
    const uint32_t sB = sA + 30720;               // 3 stages x 10240
    const int t = threadIdx.x, lane = t & 31, wid = t >> 5;
    const int wm = wid & 3, wn = wid >> 2;
    const int b  = blockIdx.z;
    const int m0 = blockIdx.y * 128;
    const int n0 = blockIdx.x * 128;
    const int Kp = 2 * Kcore;
    const __nv_bfloat16* Ab = A2 + (long long)b * Abs + (long long)m0 * Kp;
    const __nv_bfloat16* Bb = B2 + (long long)b * Bbs + (long long)n0 * Kp;

    float acc[2][8][4];
#pragma unroll
    for (int i = 0; i < 2; i++)
#pragma unroll
        for (int j = 0; j < 8; j++)
#pragma unroll
            for (int r = 0; r < 4; r++) acc[i][j][r] = 0.f;

    const int nchseg = Kcore >> 5;
    auto ldch = [&](int gc) {
        const int seg = (gc >= nchseg) + (gc >= 2 * nchseg);
        const int cc  = gc - seg * nchseg;
        const int aco = (seg == 1 ? Kcore : 0) + cc * 32;
        const int bco = (seg == 2 ? Kcore : 0) + cc * 32;
        const uint32_t ao = sA + (gc % 3) * 10240;
        const uint32_t bo = sB + (gc % 3) * 10240;
#pragma unroll
        for (int r = 0; r < 2; r++) {
            int f = t + 256 * r, row = f >> 2, kq = f & 3;
            CP_ASYNC(ao + (uint32_t)(row * 80 + kq * 16),
                     Ab + (long long)row * Kp + aco + kq * 8);
            CP_ASYNC(bo + (uint32_t)(row * 80 + kq * 16),
                     Bb + (long long)row * Kp + bco + kq * 8);
        }
        CP_COMMIT();
    };

    const int NC = 3 * nchseg;
    ldch(0);
    ldch(1);
    for (int gc = 0; gc < NC; gc++) {
        if (gc + 1 < NC) CP_WAIT1(); else CP_WAIT0();
        __syncthreads();
        if (gc + 2 < NC) ldch(gc + 2);
        const uint32_t ao = sA + (gc % 3) * 10240;
        const uint32_t bo = sB + (gc % 3) * 10240;
#pragma unroll
        for (int ks = 0; ks < 2; ks++) {
            const int kb = ks * 16;
            uint32_t af[2][4];
#pragma unroll
            for (int i = 0; i < 2; i++) {
                int row = wm * 32 + i * 16 + (lane & 7) + ((lane >> 3) & 1) * 8;
                int col = kb + ((lane >> 4) & 1) * 8;
                LDM_X4(af[i][0], af[i][1], af[i][2], af[i][3],
                       ao + (uint32_t)(row * 80 + col * 2));
            }
            uint32_t bfr[8][2];
#pragma unroll
            for (int jp = 0; jp < 4; jp++) {
                int n = wn * 64 + jp * 16 + (lane & 7) + ((lane >> 4) & 1) * 8;
                int k = kb + ((lane >> 3) & 1) * 8;
                LDM_X4(bfr[2 * jp][0], bfr[2 * jp][1],
                       bfr[2 * jp + 1][0], bfr[2 * jp + 1][1],
                       bo + (uint32_t)(n * 80 + k * 2));
            }
#pragma unroll
            for (int i = 0; i < 2; i++)
#pragma unroll
                for (int j = 0; j < 8; j++)
                    MMA16816(acc[i][j], af[i], bfr[j]);
        }
        __syncthreads();
    }

    float* Cb = C + (long long)b * Cbs;
    const float* Rb = resid ? resid + (long long)b * Rbs : nullptr;
#pragma unroll
    for (int i = 0; i < 2; i++)
#pragma unroll
        for (int h = 0; h < 2; h++) {
            int m = m0 + wm * 32 + i * 16 + (lane >> 2) + h * 8;
            float bi = bias  ? bias[m]  : 0.f;
            float sc = scale ? scale[m] : 1.f;
            float ofv = off  ? off[m]   : 0.f;
            float* crow = Cb + (long long)m * Ncols;
            const float* rrow = Rb ? Rb + (long long)m * Ncols : nullptr;
#pragma unroll
            for (int j = 0; j < 8; j++) {
                int col = n0 + wn * 64 + j * 8 + (lane & 3) * 2;
                float2 v = make_float2(acc[i][j][h * 2 + 0] + bi,
                                       acc[i][j][h * 2 + 1] + bi);
                if (scale) {
                    v.x = fmaxf(v.x, 0.f) * sc + ofv;
                    v.y = fmaxf(v.y, 0.f) * sc + ofv;
                }
                if (rrow) {
                    float2 rv = *(const float2*)(rrow + col);
                    v.x += rv.x; v.y += rv.y;
                }
                *(float2*)(crow + col) = v;
            }
        }
}

// ===========================================================================
// hconv_tap: conv KSxKS (pad KS/2) as per-tap shifted GEMMs, Kcore=128/tap.
// W2t [tap][MT][256] (hi|lo); Bsplit [B][4096][256] (hi|lo).
// ===========================================================================
template <int KS, int MT>
__global__ void __launch_bounds__(256) hconv_tap(
    const __nv_bfloat16* __restrict__ W2t, const __nv_bfloat16* __restrict__ Bsplit,
    float* __restrict__ out,
    const float* __restrict__ bias, const float* __restrict__ scale,
    const float* __restrict__ off, long long out_bstride)
{
    constexpr int P    = KS / 2;
    constexpr int TAPS = KS * KS;
    constexpr int NC   = TAPS * 12;          // 3 segs x 4 chunks per tap
    constexpr int WM_N = MT / 32;
    constexpr int WN_N = 8 / WM_N;
    constexpr int NJ   = 128 / (WN_N * 8);
    constexpr int ASTG = MT * 80;
    extern __shared__ __align__(16) char smbuf[];
    const uint32_t sA = smem_u32(smbuf);
    const uint32_t sB = sA + 3 * ASTG;
    const int t = threadIdx.x, lane = t & 31, wid = t >> 5;
    const int wm = wid % WM_N, wn = wid / WM_N;
    const int b  = blockIdx.z;
    const int n0 = blockIdx.x * 128;
    const __nv_bfloat16* Bb = Bsplit + (long long)b * (4096LL * 256);

    float acc[2][NJ][4];
#pragma unroll
    for (int i = 0; i < 2; i++)
#pragma unroll
        for (int j = 0; j < NJ; j++)
#pragma unroll
            for (int r = 0; r < 4; r++) acc[i][j][r] = 0.f;

    auto ldch = [&](int gc) {
        const int tap = gc / 12;
        const int r12 = gc - tap * 12;
        const int seg = r12 >> 2;
        const int cc  = r12 & 3;
        const int aco = (seg == 1 ? 128 : 0) + cc * 32;
        const int bco = (seg == 2 ? 128 : 0) + cc * 32;
        const int dy  = tap / KS - P, dx = tap - (tap / KS) * KS - P;
        const int shift = dy * 64 + dx;
        const uint32_t ao = sA + (gc % 3) * ASTG;
        const uint32_t bo = sB + (gc % 3) * 10240;
#pragma unroll
        for (int r = 0; r < MT / 64; r++) {
            int f = t + 256 * r, row = f >> 2, kq = f & 3;
            CP_ASYNC(ao + (uint32_t)(row * 80 + kq * 16),
                     W2t + (long long)tap * (MT * 256) + (long long)row * 256
                         + aco + kq * 8);
        }
#pragma unroll
        for (int r = 0; r < 2; r++) {
            int f = t + 256 * r, row = f >> 2, kq = f & 3;
            int gpix = n0 + row;
            int y = gpix >> 6, x = gpix & 63;
            bool ok = ((unsigned)(y + dy) < 64u) && ((unsigned)(x + dx) < 64u);
            int spix = ok ? (gpix + shift) : 0;
            uint32_t sz = ok ? 16u : 0u;
            CP_ASYNC_Z(bo + (uint32_t)(row * 80 + kq * 16),
                       Bb + (long long)spix * 256 + bco + kq * 8, sz);
        }
        CP_COMMIT();
    };

    ldch(0);
    ldch(1);
    for (int gc = 0; gc < NC; gc++) {
        if (gc + 1 < NC) CP_WAIT1(); else CP_WAIT0();
        __syncthreads();
        if (gc + 2 < NC) ldch(gc + 2);
        const uint32_t ao = sA + (gc % 3) * ASTG;
        const uint32_t bo = sB + (gc % 3) * 10240;
#pragma unroll
        for (int ks = 0; ks < 2; ks++) {
            const int kb = ks * 16;
            uint32_t af[2][4];
#pragma unroll
            for (int i = 0; i < 2; i++) {
                int row = wm * 32 + i * 16 + (lane & 7) + ((lane >> 3) & 1) * 8;
                int col = kb + ((lane >> 4) & 1) * 8;
                LDM_X4(af[i][0], af[i][1], af[i][2], af[i][3],
                       ao + (uint32_t)(row * 80 + col * 2));
            }
            uint32_t bfr[NJ][2];
#pragma unroll
            for (int jp = 0; jp < NJ / 2; jp++) {
                int n = wn * (NJ * 8) + jp * 16 + (lane & 7) + ((lane >> 4) & 1) * 8;
                int k = kb + ((lane >> 3) & 1) * 8;
                LDM_X4(bfr[2 * jp][0], bfr[2 * jp][1],
                       bfr[2 * jp + 1][0], bfr[2 * jp + 1][1],
                       bo + (uint32_t)(n * 80 + k * 2));
            }
#pragma unroll
            for (int i = 0; i < 2; i++)
#pragma unroll
                for (int j = 0; j < NJ; j++)
                    MMA16816(acc[i][j], af[i], bfr[j]);
        }
        __syncthreads();
    }

    float* Ob = out + (long long)b * out_bstride;
#pragma unroll
    for (int i = 0; i < 2; i++)
#pragma unroll
        for (int h = 0; h < 2; h++) {
            int m = wm * 32 + i * 16 + (lane >> 2) + h * 8;
            float bi = bias[m];
            float sc = scale ? scale[m] : 1.f;
            float ofv = off ? off[m] : 0.f;
            float* crow = Ob + (long long)m * 4096;
#pragma unroll
            for (int j = 0; j < NJ; j++) {
                int col = n0 + wn * (NJ * 8) + j * 8 + (lane & 3) * 2;
                float2 v = make_float2(acc[i][j][h * 2 + 0] + bi,
                                       acc[i][j][h * 2 + 1] + bi);
                if (scale) {
                    v.x = fmaxf(v.x, 0.f) * sc + ofv;
                    v.y = fmaxf(v.y, 0.f) * sc + ofv;
                }
                *(float2*)(crow + col) = v;
            }
        }
}

// ===========================================================================
// prep kernels (all 2-segment [hi|lo])
// ===========================================================================
__global__ void wsplit5_k(const float* s0, const float* s1, const float* s2,
                          const float* s3, const float* s4,
                          __nv_bfloat16* d0, __nv_bfloat16* d1, __nv_bfloat16* d2,
                          __nv_bfloat16* d3, __nv_bfloat16* d4)
{
    const int seg = blockIdx.y;
    const float* src; __nv_bfloat16* dst; int K, total;
    switch (seg) {
        case 0: src = s0; dst = d0; K = 256; total = 32768; break;
        case 1: src = s1; dst = d1; K = 256; total = 32768; break;
        case 2: src = s2; dst = d2; K = 256; total = 32768; break;
        case 3: src = s3; dst = d3; K = 256; total = 32768; break;
        default: src = s4; dst = d4; K = 128; total = 16384; break;
    }
    int i = blockIdx.x * 256 + threadIdx.x;
    if (i >= total) return;
    int m = i / K, k = i - m * K;
    __nv_bfloat16 h, l; bsplit(src[i], h, l);
    __nv_bfloat16* o = dst + (long long)m * 2 * K + k;
    o[0] = h; o[K] = l;
}

// conv weight split: src OIHW f32 [Cout,128,KS2] -> dst [tap][Cout][256] (hi|lo)
__global__ void wsplit_tap_k(const float* __restrict__ src, __nv_bfloat16* __restrict__ dst,
                             int Cout, int KS2, int total)
{
    int i = blockIdx.x * 256 + threadIdx.x;
    if (i >= total) return;
    int co = i / (128 * KS2);
    int rem = i - co * 128 * KS2;
    int ci = rem / KS2;
    int tap = rem - ci * KS2;
    __nv_bfloat16 h, l; bsplit(src[i], h, l);
    __nv_bfloat16* o = dst + (long long)tap * Cout * 256 + (long long)co * 256 + ci;
    o[0] = h; o[128] = l;
}

// transpose+split: in [B,R,Ncol] f32 -> out [B,Ncol,2R] bf16 (hi|lo)
__global__ void tsplit2_k(const float* __restrict__ in, __nv_bfloat16* __restrict__ out,
                          int R, int Ncol)
{
    __shared__ float tile[32][33];
    const int b = blockIdx.z, r0 = blockIdx.y * 32, n0 = blockIdx.x * 32;
    const int tx = threadIdx.x & 31, ty = threadIdx.x >> 5;
    const float* ib = in + (long long)b * R * Ncol;
#pragma unroll
    for (int p = 0; p < 4; p++)
        tile[ty + 8 * p][tx] = ib[(long long)(r0 + ty + 8 * p) * Ncol + n0 + tx];
    __syncthreads();
    __nv_bfloat16* ob = out + (long long)b * Ncol * 2 * R;
#pragma unroll
    for (int p = 0; p < 4; p++) {
        int n = n0 + ty + 8 * p, r = r0 + tx;
        float x = tile[tx][ty + 8 * p];
        __nv_bfloat16 h, l; bsplit(x, h, l);
        __nv_bfloat16* o = ob + (long long)n * 2 * R;
        o[r] = h; o[R + r] = l;
    }
}

// attn2: simp [B*1024,128] f32 -> [B,1024,256] bf16 (hi|lo)
__global__ void split2row_k(const float* __restrict__ in, __nv_bfloat16* __restrict__ out)
{
    int i = blockIdx.x * 256 + threadIdx.x;
    float x = in[i];
    __nv_bfloat16 h, l; bsplit(x, h, l);
    long long row = i >> 7; int c = i & 127;
    __nv_bfloat16* o = out + row * 256 + c;
    o[0] = h; o[128] = l;
}

// fused difsim: absd f32 AND difcat split operand [B,4096,512] (hi(256)|lo(256))
__global__ void difsim_split_k(const float* __restrict__ r1, const float* __restrict__ r2,
                               const float* __restrict__ sim,
                               __nv_bfloat16* __restrict__ dsplit,
                               float* __restrict__ absd)
{
    __shared__ float f1s[32][33], f2s[32][33], d1s[32][33], d2s[32][33], ss[32];
    const int b  = blockIdx.z;
    const int c0 = blockIdx.y * 32;
    const int n0 = blockIdx.x * 32;
    const int t  = threadIdx.x;
    const int tx = t & 31, ty = t >> 5;
    const long long BS = 524288;
    const float* r1b = r1 + (long long)b * BS;
    const float* r2b = r2 + (long long)b * BS;
#pragma unroll
    for (int r = 0; r < 4; r++) {
        int n = ty + 8 * r;
        f1s[n][tx] = r1b[(long long)(n0 + n) * 128 + c0 + tx];
        f2s[n][tx] = r2b[(long long)(n0 + n) * 128 + c0 + tx];
    }
    if (t < 32) ss[t] = sim[b * 4096 + n0 + t];
    __syncthreads();
#pragma unroll
    for (int r = 0; r < 4; r++) {
        int cl = ty + 8 * r;
        int c = c0 + cl;
        int n = n0 + tx;
        float rv1 = r1b[(long long)c * 4096 + n];
        float rv2 = r2b[(long long)c * 4096 + n];
        float s  = ss[tx];
        float f1 = f1s[tx][cl];
        float f2 = f2s[tx][cl];
        float omns = 1.f - s;
        d1s[cl][tx] = f1 * omns + rv1;
        d2s[cl][tx] = f2 * omns + rv2;
        absd[(long long)b * BS + (long long)c * 4096 + n] =
            fabsf((f1 - f2) * s + rv1 - rv2);
    }
    __syncthreads();
#pragma unroll
    for (int p = 0; p < 4; p++) {
        int nl = ty + 8 * p;
        float d1 = d1s[tx][nl];
        float d2 = d2s[tx][nl];
        __nv_bfloat16 h1, l1, h2, l2;
        bsplit(d1, h1, l1);
        bsplit(d2, h2, l2);
        __nv_bfloat16* orow = dsplit + (long long)b * (4096LL * 512)
                            + (long long)(n0 + nl) * 512;
        orow[c0 + tx]       = h1;
        orow[128 + c0 + tx] = h2;
        orow[256 + c0 + tx] = l1;
        orow[384 + c0 + tx] = l2;
    }
}

// fused column softmax: stats + normalize + split -> aT2 [B,4096,2048] (hi|lo)
// grid (16, 4), block 1024 (c=tid&63 column, g=tid>>6 row group)
__global__ void colsoftmax_k(const float* __restrict__ lt,
                             __nv_bfloat16* __restrict__ out)
{
    __shared__ float smx[16][65], ssm[16][65];
    __shared__ float cmx[64], csi[64];
    const int b = blockIdx.y;
    const int c = threadIdx.x & 63, g = threadIdx.x >> 6;
    const int col = blockIdx.x * 64 + c;
    const float* p = lt + (long long)b * 4194304 + col;
    float mx = -1e30f, sm = 0.f;
    for (int m = g; m < 4096; m += 16) {
        float x = p[(long long)m * 1024];
        float nm = fmaxf(mx, x);
        sm = sm * __expf(mx - nm) + __expf(x - nm);
        mx = nm;
    }
    smx[g][c] = mx; ssm[g][c] = sm;
    __syncthreads();
    if (g == 0) {
        float MX = smx[0][c], SM = ssm[0][c];
#pragma unroll
        for (int k = 1; k < 16; k++) {
            float m2 = smx[k][c], s2 = ssm[k][c];
            float nm = fmaxf(MX, m2);
            SM = SM * __expf(MX - nm) + s2 * __expf(m2 - nm);
            MX = nm;
        }
        cmx[c] = MX;
        csi[c] = 1.f / SM;
    }
    __syncthreads();
    const float MX = cmx[c], SI = csi[c];
    __nv_bfloat16* ob = out + (long long)b * (4096LL * 2048) + col;
    for (int m = g; m < 4096; m += 16) {
        float e = __expf(p[(long long)m * 1024] - MX) * SI;
        __nv_bfloat16 h, l; bsplit(e, h, l);
        ob[(long long)m * 2048]        = h;
        ob[(long long)m * 2048 + 1024] = l;
    }
}

// ===========================================================================
// scalar auxiliary kernels
// ===========================================================================
__global__ void cos_k(const float* __restrict__ r1, const float* __restrict__ r2,
                      float* __restrict__ sim)
{
    int gid  = blockIdx.x * blockDim.x + threadIdx.x;
    int wid  = gid >> 5;
    int lane = gid & 31;
    if (wid >= 4 * 4096) return;
    const float* a = r1 + (long long)wid * 128;
    const float* c = r2 + (long long)wid * 128;
    float dot = 0.f, na = 0.f, nb = 0.f;
#pragma unroll
    for (int i = 0; i < 4; i++) {
        float x = a[lane + 32 * i], y = c[lane + 32 * i];
        dot += x * y; na += x * x; nb += y * y;
    }
#pragma unroll
    for (int o = 16; o; o >>= 1) {
        dot += __shfl_xor_sync(0xffffffffu, dot, o);
        na  += __shfl_xor_sync(0xffffffffu, na,  o);
        nb  += __shfl_xor_sync(0xffffffffu, nb,  o);
    }
    if (lane == 0)
        sim[wid] = dot / fmaxf(sqrtf(na) * sqrtf(nb), 1e-8f);
}

__global__ void pool_k(const float* __restrict__ absd, float* __restrict__ simp)
{
    int i = blockIdx.x * 256 + threadIdx.x;
    if (i >= 524288) return;
    int wp = i & 31, hp = (i >> 5) & 31, bc = i >> 10;
    const float* a = absd + (long long)bc * 4096 + (hp * 2) * 64 + wp * 2;
    simp[i] = 0.25f * (a[0] + a[1] + a[64] + a[65]);
}

__global__ void resize_k(const float* __restrict__ in, float* __restrict__ out)
{
    long long i = (long long)blockIdx.x * 256 + threadIdx.x;
    if (i >= 8388608LL) return;
    int x = (int)(i & 127), y = (int)((i >> 7) & 127);
    long long bc = i >> 14;
    float sx = (x + 0.5f) * 0.5f - 0.5f;
    float sy = (y + 0.5f) * 0.5f - 0.5f;
    int x0 = (int)floorf(sx), y0 = (int)floorf(sy);
    float fx = sx - x0, fy = sy - y0;
    int x1 = min(x0 + 1, 63), y1 = min(y0 + 1, 63);
    x0 = max(x0, 0); y0 = max(y0, 0);
    const float* p = in + bc * 4096;
    float v = (1.f - fy) * ((1.f - fx) * p[y0 * 64 + x0] + fx * p[y0 * 64 + x1])
            +        fy  * ((1.f - fx) * p[y1 * 64 + x0] + fx * p[y1 * 64 + x1]);
    out[i] = v;
}

// ---------------------------------------------------------------------------
extern "C" void kernel_launch(void* const* d_in, const int* in_sizes, int n_in,
                              void* d_out, int out_size)
{
    (void)in_sizes; (void)n_in; (void)out_size;
    const float* t1      = (const float*)d_in[0];
    const float* t2      = (const float*)d_in[1];
    const float* t1_w    = (const float*)d_in[2];
    const float* t1_b    = (const float*)d_in[3];
    const float* t2_w    = (const float*)d_in[4];
    const float* t2_b    = (const float*)d_in[5];
    const float* df_res_w = (const float*)d_in[6];
    const float* df_res_b = (const float*)d_in[7];
    const float* df_res_s = (const float*)d_in[8];
    const float* df_res_o = (const float*)d_in[9];
    const float* df_b0_w = (const float*)d_in[10];
    const float* df_b0_b = (const float*)d_in[11];
    const float* df_b0_s = (const float*)d_in[12];
    const float* df_b0_o = (const float*)d_in[13];
    const float* df_b1_w = (const float*)d_in[14];
    const float* df_b1_b = (const float*)d_in[15];
    const float* df_b1_s = (const float*)d_in[16];
    const float* df_b1_o = (const float*)d_in[17];
    const float* df_fu_w = (const float*)d_in[18];
    const float* df_fu_b = (const float*)d_in[19];
    const float* df_fu_s = (const float*)d_in[20];
    const float* df_fu_o = (const float*)d_in[21];
    const float* br1_w   = (const float*)d_in[22];
    const float* br1_b   = (const float*)d_in[23];
    const float* br2_w   = (const float*)d_in[24];
    const float* br2_b   = (const float*)d_in[25];
    const float* fu_w    = (const float*)d_in[26];
    const float* fu_b    = (const float*)d_in[27];
    const float* fu_s    = (const float*)d_in[28];
    const float* fu_o    = (const float*)d_in[29];
    float* out = (float*)d_out;

    float* S;
    cudaGetSymbolAddress((void**)&S, g_scratch);
    __nv_bfloat16* G;
    cudaGetSymbolAddress((void**)&G, g_bf);

    cudaFuncSetAttribute(hmma_gemm, cudaFuncAttributeMaxDynamicSharedMemorySize, 61440);
    cudaFuncSetAttribute(hconv_tap<3, 64>,  cudaFuncAttributeMaxDynamicSharedMemorySize, 46080);
    cudaFuncSetAttribute(hconv_tap<5, 64>,  cudaFuncAttributeMaxDynamicSharedMemorySize, 46080);
    cudaFuncSetAttribute(hconv_tap<3, 128>, cudaFuncAttributeMaxDynamicSharedMemorySize, 61440);
    cudaFuncSetAttribute(hconv_tap<5, 128>, cudaFuncAttributeMaxDynamicSharedMemorySize, 61440);

    float* res1    = S + F_RES1;
    float* res2    = S + F_RES2;
    float* sim     = S + F_SIM;
    float* absd    = S + F_ABSD;
    float* simp    = S + F_SIMP;
    float* rbuf    = S + F_R;
    float* b0b1    = S + F_B0B1;
    float* dif     = S + F_DIF;
    float* inc     = S + F_INC;
    float* logitsT = S + F_LOG;
    float* acat    = S + F_ACAT;
    float* fuse    = S + F_FUSE;

    const long long S128 = 128LL * 4096;
    const long long S256 = 256LL * 4096;

    // 0: all five 1x1 weight splits
    wsplit5_k<<<dim3(128, 5), 256>>>(t1_w, t2_w, df_res_w, fu_w, df_fu_w,
                                     G + W_T1W2, G + W_T2W2, G + W_RESW2,
                                     G + W_FUW2, G + W_DFUW2);
    // conv tap weight splits
    wsplit_tap_k<<<288,  256>>>(df_b0_w, G + W_B0T,  64,  9,  73728);
    wsplit_tap_k<<<800,  256>>>(df_b1_w, G + W_B1T,  64,  25, 204800);
    wsplit_tap_k<<<576,  256>>>(br1_w,   G + W_BR1T, 128, 9,  147456);
    wsplit_tap_k<<<1600, 256>>>(br2_w,   G + W_BR2T, 128, 25, 409600);
    // input splits
    tsplit2_k<<<dim3(128, 8, 4), 256>>>(t1, G + G_T3A, 256, 4096);
    tsplit2_k<<<dim3(128, 8, 4), 256>>>(t2, G + G_T3B, 256, 4096);
    // 1. res1/res2 = 1x1 (256->128) + bias
    hmma_gemm<<<dim3(32, 1, 4), 256, 61440>>>(G + W_T1W2, G + G_T3A, res1,
                                              t1_b, nullptr, nullptr, nullptr,
                                              256, 4096, 0, 4096LL * 512, S128, 0);
    hmma_gemm<<<dim3(32, 1, 4), 256, 61440>>>(G + W_T2W2, G + G_T3B, res2,
                                              t2_b, nullptr, nullptr, nullptr,
                                              256, 4096, 0, 4096LL * 512, S128, 0);
    // 2-4. cosine, fused dif-split (into G_T3A), avgpool, attn operands
    cos_k<<<2048, 256>>>(res1, res2, sim);
    difsim_split_k<<<dim3(128, 4, 4), 256>>>(res1, res2, sim, G + G_T3A, absd);
    pool_k<<<2048, 256>>>(absd, simp);
    split2row_k<<<2048, 256>>>(simp, G + G_ATTN2);
    tsplit2_k<<<dim3(4, 32, 4), 256>>>(simp, G + G_ATTNT2, 1024, 128);
    // 5. r = stdconv 1x1 (256->128)
    hmma_gemm<<<dim3(32, 1, 4), 256, 61440>>>(G + W_RESW2, G + G_T3A, rbuf,
                                              df_res_b, df_res_s, df_res_o, nullptr,
                                              256, 4096, 0, 4096LL * 512, S128, 0);
    // 6/7. inception branches over shared rbuf-split
    tsplit2_k<<<dim3(128, 4, 4), 256>>>(rbuf, G + G_RB2, 128, 4096);
    hconv_tap<3, 64><<<dim3(32, 1, 4), 256, 46080>>>(
        G + W_B0T, G + G_RB2, b0b1, df_b0_b, df_b0_s, df_b0_o, S128);
    hconv_tap<5, 64><<<dim3(32, 1, 4), 256, 46080>>>(
        G + W_B1T, G + G_RB2, b0b1 + 64LL * 4096, df_b1_b, df_b1_s, df_b1_o, S128);
    // 8. dif = stdconv 1x1 (128->128) + r
    tsplit2_k<<<dim3(128, 4, 4), 256>>>(b0b1, G + G_BB2, 128, 4096);
    hmma_gemm<<<dim3(32, 1, 4), 256, 61440>>>(G + W_DFUW2, G + G_BB2, dif,
                                              df_fu_b, df_fu_s, df_fu_o, rbuf,
                                              128, 4096, 0, 4096LL * 256, S128, S128);
    tsplit2_k<<<dim3(128, 4, 4), 256>>>(dif, G + G_DIF2, 128, 4096);
    // --- attention branches ---
    for (int br = 0; br < 2; br++) {
        if (br == 0)
            hconv_tap<3, 128><<<dim3(32, 1, 4), 256, 61440>>>(
                G + W_BR1T, G + G_DIF2, inc, br1_b, nullptr, nullptr, S128);
        else
            hconv_tap<5, 128><<<dim3(32, 1, 4), 256, 61440>>>(
                G + W_BR2T, G + G_DIF2, inc, br2_b, nullptr, nullptr, S128);
        tsplit2_k<<<dim3(128, 4, 4), 256>>>(inc, G + G_INCT2, 128, 4096);
        // logitsT[b, pix, tok] = incT . attn
        hmma_gemm<<<dim3(8, 32, 4), 256, 61440>>>(G + G_INCT2, G + G_ATTN2, logitsT,
                                                  nullptr, nullptr, nullptr, nullptr,
                                                  128, 1024,
                                                  4096LL * 256, 1024LL * 256,
                                                  4096LL * 1024, 0);
        colsoftmax_k<<<dim3(16, 4), 1024>>>(logitsT, G + G_AT2);
        // out[b, c, pix] = attnT . aT + inc  -> acat half
        hmma_gemm<<<dim3(32, 1, 4), 256, 61440>>>(G + G_ATTNT2, G + G_AT2,
                                                  acat + (long long)br * S128,
                                                  nullptr, nullptr, nullptr, inc,
                                                  1024, 4096,
                                                  128LL * 2048, 4096LL * 2048,
                                                  S256, S128);
    }
    // 14. fused = stdconv 1x1 (256->128) + dif
    tsplit2_k<<<dim3(128, 8, 4), 256>>>(acat, G + G_T3A, 256, 4096);
    hmma_gemm<<<dim3(32, 1, 4), 256, 61440>>>(G + W_FUW2, G + G_T3A, fuse,
                                              fu_b, fu_s, fu_o, dif,
                                              256, 4096, 0, 4096LL * 512, S128, S128);
    // 15. bilinear x2 upsample
    resize_k<<<32768, 256>>>(fuse, out);
}